// round 6
// baseline (speedup 1.0000x reference)
#include <cuda_runtime.h>
#include <cuda_bf16.h>
#include <mma.h>
#include <cstdint>

using namespace nvcuda;

// ---------------- problem constants ----------------
#define BB 8
#define DD 512
#define T_TOT 36
#define DEMO_TT 4
#define OBS_TT 32
#define HWW 84
#define FF 128
#define NH 4
#define CH 32               // channels per head
#define DM (DEMO_TT*HWW)    // 336 demo positions
#define OM (OBS_TT*HWW)     // 2688 obs positions
#define CATP (DM+HWW)       // 420 concat positions
#define SPAT (T_TOT*HWW)    // 3024

static constexpr float INV_TEMP = 0.044194173824159216f; // 1/sqrt(512)

// ---------------- device scratch (no cudaMalloc allowed) ----------------
__device__ float g_x    [BB*DD*SPAT];    // running activation (B,512,36,84)
__device__ float g_dq   [BB*FF*DM];
__device__ float g_dk   [BB*FF*DM];
__device__ float g_dv   [BB*FF*DM];
__device__ float g_dvatt[BB*FF*DM];
__device__ float g_oq   [BB*FF*OM];
__device__ float g_ok   [BB*FF*OM];
__device__ float g_ov   [BB*FF*OM];
__device__ float g_pv   [BB*FF*OM];      // ov_att in (n*32+c, t*84+i) layout

// bf16 hi/lo split operands for tensor-core GEMMs
__device__ __nv_bfloat16 g_xhi [BB*DD*SPAT];
__device__ __nv_bfloat16 g_xlo [BB*DD*SPAT];
__device__ __nv_bfloat16 g_pvhi[BB*FF*OM];
__device__ __nv_bfloat16 g_pvlo[BB*FF*OM];
// packed qkv weights: [tensor 0..5][layer 0..1][FF*DD], tensors: dq,dk,dv,oq,ok,ov
__device__ __nv_bfloat16 g_wqhi[6*2*FF*DD];
__device__ __nv_bfloat16 g_wqlo[6*2*FF*DD];
__device__ __nv_bfloat16 g_wohi[2*DD*FF];
__device__ __nv_bfloat16 g_wolo[2*DD*FF];

// ---------------- fp32 -> bf16 hi/lo split ----------------
__global__ void cvt_pair(const float* __restrict__ s, __nv_bfloat16* __restrict__ hi,
                         __nv_bfloat16* __restrict__ lo, int n)
{
    int i = blockIdx.x * 256 + threadIdx.x;
    if (i < n) {
        float v = s[i];
        __nv_bfloat16 h = __float2bfloat16(v);
        hi[i] = h;
        lo[i] = __float2bfloat16(v - __bfloat162float(h));
    }
}

// ================= WMMA GEMM (128x128 tile, bf16 HMMA, fp32 accum) =================
// smem union: load buffers (A 128x48, B 32x136 bf16) vs epilogue stage (64x132 f32)
union SmemU {
    struct { __nv_bfloat16 A[128][48]; __nv_bfloat16 B[32][136]; } ld;
    float st[64][132];
};

// ---------------- QKV GEMM: C_w[b](128 x ncols) = W_w(128x512) * X[b](512 x ncols) ----
// extended K = 3*512 (term0: Ahi*Bhi, term1: Ahi*Blo, term2: Alo*Bhi)
__global__ __launch_bounds__(256)
void wmma_qkv(const __nv_bfloat16* __restrict__ whi, const __nv_bfloat16* __restrict__ wlo,
              const __nv_bfloat16* __restrict__ xhi, const __nv_bfloat16* __restrict__ xlo,
              float* __restrict__ Cq, float* __restrict__ Ck, float* __restrict__ Cv,
              int ncols, int ldb, long long bStride, long long cStride)
{
    __shared__ SmemU sm;
    int tid = threadIdx.x;
    int w = blockIdx.x;
    int b = blockIdx.z;
    int colBase = blockIdx.y * 128;
    bool fullTile = (colBase + 128 <= ncols);

    const __nv_bfloat16* Ahi = whi + (long long)w * (2*FF*DD);
    const __nv_bfloat16* Alo = wlo + (long long)w * (2*FF*DD);
    const __nv_bfloat16* Bhi = xhi + (long long)b * bStride;
    const __nv_bfloat16* Blo = xlo + (long long)b * bStride;
    float* C = ((w == 0) ? Cq : (w == 1) ? Ck : Cv) + (long long)b * cStride;

    int warp = tid >> 5;
    int wm = warp & 3;           // 4 warp rows of 32
    int wn = warp >> 2;          // 2 warp cols of 64

    wmma::fragment<wmma::accumulator, 16, 16, 16, float> acc[2][4];
    #pragma unroll
    for (int i = 0; i < 2; i++)
        #pragma unroll
        for (int j = 0; j < 4; j++)
            wmma::fill_fragment(acc[i][j], 0.f);

    for (int c = 0; c < 48; c++) {
        int term = c >> 4;
        int kbase = (c & 15) * 32;
        const __nv_bfloat16* Asrc = (term == 2) ? Alo : Ahi;
        const __nv_bfloat16* Bsrc = (term == 1) ? Blo : Bhi;

        // A: 128 rows x 32 k, vectorized 8-bf16 loads
        #pragma unroll
        for (int r = 0; r < 2; r++) {
            int e = tid + r*256;
            int m = e >> 2, k8 = (e & 3) * 8;
            *(uint4*)&sm.ld.A[m][k8] = *(const uint4*)&Asrc[(long long)m*DD + kbase + k8];
        }
        // B: 32 k x 128 n
        #pragma unroll
        for (int r = 0; r < 2; r++) {
            int e = tid + r*256;
            int k = e >> 4, n8 = (e & 15) * 8;
            const __nv_bfloat16* src = &Bsrc[(long long)(kbase + k)*ldb + colBase + n8];
            if (fullTile) {
                *(uint4*)&sm.ld.B[k][n8] = *(const uint4*)src;
            } else {
                #pragma unroll
                for (int q = 0; q < 8; q++)
                    sm.ld.B[k][n8 + q] = (colBase + n8 + q < ncols) ? src[q]
                                                                    : __float2bfloat16(0.f);
            }
        }
        __syncthreads();

        #pragma unroll
        for (int ks = 0; ks < 32; ks += 16) {
            wmma::fragment<wmma::matrix_a, 16, 16, 16, __nv_bfloat16, wmma::row_major> af[2];
            wmma::fragment<wmma::matrix_b, 16, 16, 16, __nv_bfloat16, wmma::row_major> bf[4];
            #pragma unroll
            for (int i = 0; i < 2; i++)
                wmma::load_matrix_sync(af[i], &sm.ld.A[wm*32 + i*16][ks], 48);
            #pragma unroll
            for (int j = 0; j < 4; j++)
                wmma::load_matrix_sync(bf[j], &sm.ld.B[ks][wn*64 + j*16], 136);
            #pragma unroll
            for (int i = 0; i < 2; i++)
                #pragma unroll
                for (int j = 0; j < 4; j++)
                    wmma::mma_sync(acc[i][j], af[i], bf[j], acc[i][j]);
        }
        __syncthreads();
    }

    // epilogue in two 64-row halves through smem stage
    #pragma unroll
    for (int h = 0; h < 2; h++) {
        if (wm >= h*2 && wm < h*2 + 2) {
            #pragma unroll
            for (int i = 0; i < 2; i++)
                #pragma unroll
                for (int j = 0; j < 4; j++)
                    wmma::store_matrix_sync(&sm.st[(wm - h*2)*32 + i*16][wn*64 + j*16],
                                            acc[i][j], 132, wmma::mem_row_major);
        }
        __syncthreads();
        for (int e = tid; e < 64*128; e += 256) {
            int m = e >> 7, col = e & 127;
            int gc = colBase + col;
            if (gc < ncols) C[(long long)(h*64 + m)*ncols + gc] = sm.st[m][col];
        }
        __syncthreads();
    }
}

// ---- output projection: x[b, rowBase+m, DM+col] += relu(wo(512x128) @ pv[b](128x2688)) ----
// extended K = 3*128
__global__ __launch_bounds__(256)
void wmma_wo(const __nv_bfloat16* __restrict__ whi, const __nv_bfloat16* __restrict__ wlo,
             const __nv_bfloat16* __restrict__ phi, const __nv_bfloat16* __restrict__ plo,
             float* __restrict__ x)
{
    __shared__ SmemU sm;
    int tid = threadIdx.x;
    int rowBase = blockIdx.x * 128;
    int b = blockIdx.z;
    int colBase = blockIdx.y * 128;

    const __nv_bfloat16* Bhi = phi + (long long)b * (FF*OM);
    const __nv_bfloat16* Blo = plo + (long long)b * (FF*OM);

    int warp = tid >> 5;
    int wm = warp & 3;
    int wn = warp >> 2;

    wmma::fragment<wmma::accumulator, 16, 16, 16, float> acc[2][4];
    #pragma unroll
    for (int i = 0; i < 2; i++)
        #pragma unroll
        for (int j = 0; j < 4; j++)
            wmma::fill_fragment(acc[i][j], 0.f);

    for (int c = 0; c < 12; c++) {
        int term = c >> 2;
        int kbase = (c & 3) * 32;
        const __nv_bfloat16* Asrc = ((term == 2) ? wlo : whi);
        const __nv_bfloat16* Bsrc = (term == 1) ? Blo : Bhi;

        #pragma unroll
        for (int r = 0; r < 2; r++) {
            int e = tid + r*256;
            int m = e >> 2, k8 = (e & 3) * 8;
            *(uint4*)&sm.ld.A[m][k8] =
                *(const uint4*)&Asrc[(long long)(rowBase + m)*FF + kbase + k8];
        }
        #pragma unroll
        for (int r = 0; r < 2; r++) {
            int e = tid + r*256;
            int k = e >> 4, n8 = (e & 15) * 8;
            *(uint4*)&sm.ld.B[k][n8] =
                *(const uint4*)&Bsrc[(long long)(kbase + k)*OM + colBase + n8];
        }
        __syncthreads();

        #pragma unroll
        for (int ks = 0; ks < 32; ks += 16) {
            wmma::fragment<wmma::matrix_a, 16, 16, 16, __nv_bfloat16, wmma::row_major> af[2];
            wmma::fragment<wmma::matrix_b, 16, 16, 16, __nv_bfloat16, wmma::row_major> bf[4];
            #pragma unroll
            for (int i = 0; i < 2; i++)
                wmma::load_matrix_sync(af[i], &sm.ld.A[wm*32 + i*16][ks], 48);
            #pragma unroll
            for (int j = 0; j < 4; j++)
                wmma::load_matrix_sync(bf[j], &sm.ld.B[ks][wn*64 + j*16], 136);
            #pragma unroll
            for (int i = 0; i < 2; i++)
                #pragma unroll
                for (int j = 0; j < 4; j++)
                    wmma::mma_sync(acc[i][j], af[i], bf[j], acc[i][j]);
        }
        __syncthreads();
    }

    #pragma unroll
    for (int h = 0; h < 2; h++) {
        if (wm >= h*2 && wm < h*2 + 2) {
            #pragma unroll
            for (int i = 0; i < 2; i++)
                #pragma unroll
                for (int j = 0; j < 4; j++)
                    wmma::store_matrix_sync(&sm.st[(wm - h*2)*32 + i*16][wn*64 + j*16],
                                            acc[i][j], 132, wmma::mem_row_major);
        }
        __syncthreads();
        for (int e = tid; e < 64*128; e += 256) {
            int m = e >> 7, col = e & 127;
            long long xi = ((long long)(b*DD + rowBase + h*64 + m))*SPAT + DM + colBase + col;
            x[xi] += fmaxf(sm.st[m][col], 0.f);
        }
        __syncthreads();
    }
}

// ---------------- fused demo attention + dv_att ----------------
__global__ void demo_attn_kernel(const float* __restrict__ dk,
                                 const float* __restrict__ dq,
                                 const float* __restrict__ dv,
                                 float* __restrict__ dvatt)
{
    int i = blockIdx.x;      // 0..335
    int n = blockIdx.y;      // head
    int b = blockIdx.z;
    const long long base = ((long long)b*FF + n*CH) * DM;
    const float* Kp = dk + base;
    const float* Qp = dq + base;
    const float* Vp = dv + base;

    __shared__ float kv[CH];
    __shared__ float logit[DM];
    __shared__ float red[128];
    __shared__ float part[CH*128];
    int tid = threadIdx.x;

    if (tid < CH) kv[tid] = Kp[tid*DM + i];
    __syncthreads();

    int nvalid = (i / HWW + 1) * HWW;   // causal block mask

    float lmax = -1e30f;
    for (int j = tid; j < nvalid; j += 128) {
        float s = 0.f;
        #pragma unroll
        for (int c = 0; c < CH; c++) s += kv[c] * Qp[c*DM + j];
        s *= INV_TEMP;
        logit[j] = s;
        lmax = fmaxf(lmax, s);
    }
    red[tid] = lmax; __syncthreads();
    for (int o = 64; o > 0; o >>= 1) { if (tid < o) red[tid] = fmaxf(red[tid], red[tid+o]); __syncthreads(); }
    float m = red[0];
    __syncthreads();

    float lsum = 0.f;
    for (int j = tid; j < nvalid; j += 128) {
        float e = __expf(logit[j] - m);
        logit[j] = e;
        lsum += e;
    }
    red[tid] = lsum; __syncthreads();
    for (int o = 64; o > 0; o >>= 1) { if (tid < o) red[tid] += red[tid+o]; __syncthreads(); }
    float inv = 1.f / red[0];
    __syncthreads();

    float acc[CH] = {};
    for (int j = tid; j < nvalid; j += 128) {
        float p = logit[j];
        #pragma unroll
        for (int c = 0; c < CH; c++) acc[c] += p * Vp[c*DM + j];
    }
    #pragma unroll
    for (int c = 0; c < CH; c++) part[c*128 + tid] = acc[c];
    __syncthreads();
    for (int o = 64; o > 0; o >>= 1) {
        for (int idx = tid; idx < CH*o; idx += 128) {
            int c = idx / o, t = idx % o;
            part[c*128 + t] += part[c*128 + t + o];
        }
        __syncthreads();
    }
    if (tid < CH) dvatt[base + tid*DM + i] = part[tid*128] * inv;
}

// ---------------- fused obs attention per (b,t,n) ----------------
#define PCH 64
__global__ void obs_attn_kernel(const float* __restrict__ dk,
                                const float* __restrict__ dvatt,
                                const float* __restrict__ ok,
                                const float* __restrict__ ov,
                                const float* __restrict__ oq,
                                float* __restrict__ pv)
{
    int n = blockIdx.x, t = blockIdx.y, b = blockIdx.z;
    const long long obase = ((long long)b*FF + n*CH) * OM + (long long)t*HWW;
    const long long dbase = ((long long)b*FF + n*CH) * DM;

    __shared__ float qs[CH][HWW];     // 32x84
    __shared__ float ks[CH][PCH];     // 32x64
    __shared__ float vs[CH][PCH];
    __shared__ float S[PCH][HWW+1];   // 64x85

    int tid = threadIdx.x;
    int tx = tid % 16, ty = tid / 16;

    for (int l = tid; l < CH*HWW; l += 256) {
        int c = l / HWW, j = l % HWW;
        qs[c][j] = oq[obase + (long long)c*OM + j];
    }

    float acc[2][6] = {};

    for (int p0 = 0; p0 < CATP; p0 += PCH) {
        for (int l = tid; l < CH*PCH; l += 256) {
            int c = l / PCH, pl = l % PCH;
            int p = p0 + pl;
            float kk = 0.f, vv = 0.f;
            if (p < DM) {
                kk = dk   [dbase + (long long)c*DM + p];
                vv = dvatt[dbase + (long long)c*DM + p];
            } else if (p < CATP) {
                kk = ok[obase + (long long)c*OM + (p - DM)];
                vv = ov[obase + (long long)c*OM + (p - DM)];
            }
            ks[c][pl] = kk; vs[c][pl] = vv;
        }
        __syncthreads();

        {
            float sa[4][6] = {};
            #pragma unroll
            for (int k = 0; k < CH; k++) {
                float a[4], bq[6];
                #pragma unroll
                for (int pp = 0; pp < 4; pp++) a[pp] = ks[k][ty*4 + pp];
                #pragma unroll
                for (int jj = 0; jj < 6; jj++) {
                    int j = tx*6 + jj;
                    bq[jj] = (j < HWW) ? qs[k][j] : 0.f;
                }
                #pragma unroll
                for (int pp = 0; pp < 4; pp++)
                    #pragma unroll
                    for (int jj = 0; jj < 6; jj++)
                        sa[pp][jj] += a[pp] * bq[jj];
            }
            #pragma unroll
            for (int pp = 0; pp < 4; pp++)
                #pragma unroll
                for (int jj = 0; jj < 6; jj++) {
                    int j = tx*6 + jj;
                    if (j < HWW) S[ty*4 + pp][j] = sa[pp][jj] * INV_TEMP;
                }
        }
        __syncthreads();

        {
            int row = tid >> 2;
            int l4  = tid & 3;
            float mx = -1e30f;
            for (int j = l4; j < HWW; j += 4) mx = fmaxf(mx, S[row][j]);
            mx = fmaxf(mx, __shfl_xor_sync(0xffffffffu, mx, 1));
            mx = fmaxf(mx, __shfl_xor_sync(0xffffffffu, mx, 2));
            float sum = 0.f;
            for (int j = l4; j < HWW; j += 4) {
                float e = __expf(S[row][j] - mx);
                S[row][j] = e;
                sum += e;
            }
            sum += __shfl_xor_sync(0xffffffffu, sum, 1);
            sum += __shfl_xor_sync(0xffffffffu, sum, 2);
            float iv = 1.f / sum;
            bool valid = (p0 + row) < CATP;
            for (int j = l4; j < HWW; j += 4)
                S[row][j] = valid ? S[row][j] * iv : 0.f;
        }
        __syncthreads();

        #pragma unroll 4
        for (int pl = 0; pl < PCH; pl++) {
            float v0 = vs[ty][pl];
            float v1 = vs[ty+16][pl];
            float sv[6];
            #pragma unroll
            for (int jj = 0; jj < 6; jj++) {
                int i = tx*6 + jj;
                sv[jj] = (i < HWW) ? S[pl][i] : 0.f;
            }
            #pragma unroll
            for (int jj = 0; jj < 6; jj++) {
                acc[0][jj] += v0 * sv[jj];
                acc[1][jj] += v1 * sv[jj];
            }
        }
        __syncthreads();
    }

    #pragma unroll
    for (int cc = 0; cc < 2; cc++) {
        int c = ty + 16*cc;
        #pragma unroll
        for (int jj = 0; jj < 6; jj++) {
            int i = tx*6 + jj;
            if (i < HWW) pv[obase + (long long)c*OM + i] = acc[cc][jj];
        }
    }
}

// ---------------- batchnorm over (B, T, H, W) per channel ----------------
__global__ void bn_kernel(const float* __restrict__ x, float* __restrict__ out,
                          const float* __restrict__ gamma, const float* __restrict__ beta)
{
    int ch = blockIdx.x;
    int tid = threadIdx.x;
    const long long chOff = (long long)ch * SPAT;

    double s = 0.0, s2 = 0.0;
    for (int b = 0; b < BB; b++) {
        const float* p = x + (long long)b*DD*SPAT + chOff;
        for (int idx = tid; idx < SPAT; idx += 256) {
            float v = p[idx];
            s  += v;
            s2 += (double)v * v;
        }
    }
    __shared__ double rs[256], rs2[256];
    rs[tid] = s; rs2[tid] = s2; __syncthreads();
    for (int o = 128; o > 0; o >>= 1) {
        if (tid < o) { rs[tid] += rs[tid+o]; rs2[tid] += rs2[tid+o]; }
        __syncthreads();
    }
    const double cnt = (double)BB * SPAT;
    double mean = rs[0] / cnt;
    double var  = rs2[0] / cnt - mean*mean;
    float scale = (float)((double)gamma[ch] * rsqrt(var + 1e-5));
    float mn = (float)mean;
    float bt = beta[ch];
    for (int b = 0; b < BB; b++) {
        const float* p = x   + (long long)b*DD*SPAT + chOff;
        float*       q = out + (long long)b*DD*SPAT + chOff;
        for (int idx = tid; idx < SPAT; idx += 256)
            q[idx] = scale * (p[idx] - mn) + bt;
    }
}

// ---------------- host driver ----------------
extern "C" void kernel_launch(void* const* d_in, const int* in_sizes, int n_in,
                              void* d_out, int out_size)
{
    const float* inputs  = (const float*)d_in[0];
    const float* demo_wq = (const float*)d_in[1];
    const float* demo_wk = (const float*)d_in[2];
    const float* demo_wv = (const float*)d_in[3];
    // demo_wo (d_in[4]) unused by the reference
    const float* obs_wq  = (const float*)d_in[5];
    const float* obs_wk  = (const float*)d_in[6];
    const float* obs_wv  = (const float*)d_in[7];
    const float* obs_wo  = (const float*)d_in[8];
    const float* bn_g    = (const float*)d_in[9];
    const float* bn_b    = (const float*)d_in[10];
    float* out = (float*)d_out;

    float *xp, *dqp, *dkp, *dvp, *dvattp, *oqp, *okp, *ovp, *pvp;
    __nv_bfloat16 *xhip, *xlop, *pvhip, *pvlop, *wqhip, *wqlop, *wohip, *wolop;
    cudaGetSymbolAddress((void**)&xp,     g_x);
    cudaGetSymbolAddress((void**)&dqp,    g_dq);
    cudaGetSymbolAddress((void**)&dkp,    g_dk);
    cudaGetSymbolAddress((void**)&dvp,    g_dv);
    cudaGetSymbolAddress((void**)&dvattp, g_dvatt);
    cudaGetSymbolAddress((void**)&oqp,    g_oq);
    cudaGetSymbolAddress((void**)&okp,    g_ok);
    cudaGetSymbolAddress((void**)&ovp,    g_ov);
    cudaGetSymbolAddress((void**)&pvp,    g_pv);
    cudaGetSymbolAddress((void**)&xhip,   g_xhi);
    cudaGetSymbolAddress((void**)&xlop,   g_xlo);
    cudaGetSymbolAddress((void**)&pvhip,  g_pvhi);
    cudaGetSymbolAddress((void**)&pvlop,  g_pvlo);
    cudaGetSymbolAddress((void**)&wqhip,  g_wqhi);
    cudaGetSymbolAddress((void**)&wqlop,  g_wqlo);
    cudaGetSymbolAddress((void**)&wohip,  g_wohi);
    cudaGetSymbolAddress((void**)&wolop,  g_wolo);

    cudaMemcpyAsync(xp, inputs, (size_t)BB*DD*SPAT*sizeof(float),
                    cudaMemcpyDeviceToDevice, 0);

    // convert weights: [tensor][layer][FF*DD]
    const int WT = 2*FF*DD;   // per-tensor element count (both layers)
    const float* wsrc[6] = {demo_wq, demo_wk, demo_wv, obs_wq, obs_wk, obs_wv};
    for (int t = 0; t < 6; t++)
        cvt_pair<<<WT/256, 256>>>(wsrc[t], wqhip + (long long)t*WT, wqlop + (long long)t*WT, WT);
    cvt_pair<<<WT/256, 256>>>(obs_wo, wohip, wolop, WT);

    const long long XEL = (long long)BB*DD*SPAT;
    const long long PEL = (long long)BB*FF*OM;
    const long long XB  = (long long)DD*SPAT;
    const long long QD  = (long long)FF*DM;
    const long long QO  = (long long)FF*OM;

    for (int i = 0; i < 2; i++) {
        const long long lw = (long long)i*FF*DD;

        // split x into bf16 hi/lo
        cvt_pair<<<(unsigned)((XEL + 255)/256), 256>>>(xp, xhip, xlop, (int)XEL);

        // demo QKV (tensor cores): grid (3 weights, 3 col tiles, 8 batches)
        wmma_qkv<<<dim3(3, (DM + 127)/128, BB), 256>>>(
            wqhip + lw, wqlop + lw, xhip, xlop,
            dqp, dkp, dvp, DM, SPAT, XB, QD);

        demo_attn_kernel<<<dim3(DM, NH, BB), 128>>>(dkp, dqp, dvp, dvattp);

        // obs QKV: weights 3..5, x offset DM
        wmma_qkv<<<dim3(3, OM/128, BB), 256>>>(
            wqhip + 3LL*WT + lw, wqlop + 3LL*WT + lw, xhip + DM, xlop + DM,
            oqp, okp, ovp, OM, SPAT, XB, QO);

        obs_attn_kernel<<<dim3(NH, OBS_TT, BB), 256>>>(dkp, dvattp, okp, ovp, oqp, pvp);

        // split pv, then output projection + residual + relu into x
        cvt_pair<<<(unsigned)((PEL + 255)/256), 256>>>(pvp, pvhip, pvlop, (int)PEL);
        wmma_wo<<<dim3(DD/128, OM/128, BB), 256>>>(
            wohip + lw, wolop + lw, pvhip, pvlop, xp);

        bn_kernel<<<DD, 256>>>(xp, (i == 1) ? out : xp, bn_g + i*DD, bn_b + i*DD);
    }
}

// round 7
// speedup vs baseline: 1.1121x; 1.1121x over previous
#include <cuda_runtime.h>
#include <cuda_bf16.h>
#include <mma.h>
#include <cstdint>

using namespace nvcuda;

// ---------------- problem constants ----------------
#define BB 8
#define DD 512
#define T_TOT 36
#define DEMO_TT 4
#define OBS_TT 32
#define HWW 84
#define FF 128
#define NH 4
#define CH 32               // channels per head
#define DM (DEMO_TT*HWW)    // 336 demo positions
#define OM (OBS_TT*HWW)     // 2688 obs positions
#define CATP (DM+HWW)       // 420 concat positions
#define SPAT (T_TOT*HWW)    // 3024

static constexpr float INV_TEMP = 0.044194173824159216f; // 1/sqrt(512)

// ---------------- device scratch (no cudaMalloc allowed) ----------------
__device__ float g_x    [BB*DD*SPAT];    // running activation (B,512,36,84)
__device__ float g_dq   [BB*FF*DM];
__device__ float g_dk   [BB*FF*DM];
__device__ float g_dv   [BB*FF*DM];
__device__ float g_dvatt[BB*FF*DM];
__device__ float g_oq   [BB*FF*OM];
__device__ float g_ok   [BB*FF*OM];
__device__ float g_ov   [BB*FF*OM];
__device__ float g_pv   [BB*FF*OM];      // ov_att in (n*32+c, t*84+i) layout

// bf16 hi/lo split operands for tensor-core GEMMs
__device__ __nv_bfloat16 g_xhi [BB*DD*SPAT];
__device__ __nv_bfloat16 g_xlo [BB*DD*SPAT];
__device__ __nv_bfloat16 g_pvhi[BB*FF*OM];
__device__ __nv_bfloat16 g_pvlo[BB*FF*OM];
// packed qkv weights: [tensor 0..5][layer 0..1][FF*DD], tensors: dq,dk,dv,oq,ok,ov
__device__ __nv_bfloat16 g_wqhi[6*2*FF*DD];
__device__ __nv_bfloat16 g_wqlo[6*2*FF*DD];
__device__ __nv_bfloat16 g_wohi[2*DD*FF];
__device__ __nv_bfloat16 g_wolo[2*DD*FF];

// ---------------- cp.async helpers (sm_80+ baseline features) ----------------
__device__ __forceinline__ void cpa16(void* dst_smem, const void* src) {
    uint32_t d = (uint32_t)__cvta_generic_to_shared(dst_smem);
    asm volatile("cp.async.cg.shared.global [%0], [%1], 16;" :: "r"(d), "l"(src));
}
#define CPA_COMMIT() asm volatile("cp.async.commit_group;")

// ---------------- fp32 -> bf16 hi/lo split ----------------
__global__ void cvt_pair(const float* __restrict__ s, __nv_bfloat16* __restrict__ hi,
                         __nv_bfloat16* __restrict__ lo, int n)
{
    int i = blockIdx.x * 256 + threadIdx.x;
    if (i < n) {
        float v = s[i];
        __nv_bfloat16 h = __float2bfloat16(v);
        hi[i] = h;
        lo[i] = __float2bfloat16(v - __bfloat162float(h));
    }
}

// ================= WMMA GEMM (128x128 tile, bf16 HMMA, fp32 accum) =================
// double-buffered load buffers vs epilogue stage (union — phases don't overlap)
union SmemU {
    struct { __nv_bfloat16 A[2][128][48]; __nv_bfloat16 B[2][32][136]; } ld;
    float st[64][132];
};

// ---------------- QKV GEMM: C_w[b](128 x ncols) = W_w(128x512) * X[b](512 x ncols) ----
// extended K = 3*512 (term0: Ahi*Bhi, term1: Ahi*Blo, term2: Alo*Bhi)
// NOTE: B loads are unguarded — OOB columns only feed C columns discarded at store,
// and reads stay within the x row (ldb=3024 >= colBase+128 for all tiles).
__global__ __launch_bounds__(256)
void wmma_qkv(const __nv_bfloat16* __restrict__ whi, const __nv_bfloat16* __restrict__ wlo,
              const __nv_bfloat16* __restrict__ xhi, const __nv_bfloat16* __restrict__ xlo,
              float* __restrict__ Cq, float* __restrict__ Ck, float* __restrict__ Cv,
              int ncols, int ldb, long long bStride, long long cStride)
{
    __shared__ SmemU sm;
    int tid = threadIdx.x;
    int w = blockIdx.x;
    int b = blockIdx.z;
    int colBase = blockIdx.y * 128;

    const __nv_bfloat16* Ahi = whi + (long long)w * (2*FF*DD);
    const __nv_bfloat16* Alo = wlo + (long long)w * (2*FF*DD);
    const __nv_bfloat16* Bhi = xhi + (long long)b * bStride;
    const __nv_bfloat16* Blo = xlo + (long long)b * bStride;
    float* C = ((w == 0) ? Cq : (w == 1) ? Ck : Cv) + (long long)b * cStride;

    const __nv_bfloat16* Asel[3] = {Ahi, Ahi, Alo};
    const __nv_bfloat16* Bsel[3] = {Bhi, Blo, Bhi};

    int warp = tid >> 5;
    int wm = warp & 3;           // 4 warp rows of 32
    int wn = warp >> 2;          // 2 warp cols of 64

    wmma::fragment<wmma::accumulator, 16, 16, 16, float> acc[2][4];
    #pragma unroll
    for (int i = 0; i < 2; i++)
        #pragma unroll
        for (int j = 0; j < 4; j++)
            wmma::fill_fragment(acc[i][j], 0.f);

    auto loadChunk = [&](int c, int buf) {
        int term = c >> 4;               // 16 chunks of 32 per term
        int kb = (c & 15) * 32;
        const __nv_bfloat16* As = Asel[term];
        const __nv_bfloat16* Bs = Bsel[term];
        #pragma unroll
        for (int r = 0; r < 2; r++) {
            int e = tid + r*256;
            int m = e >> 2, k8 = (e & 3) * 8;
            cpa16(&sm.ld.A[buf][m][k8], &As[(long long)m*DD + kb + k8]);
        }
        #pragma unroll
        for (int r = 0; r < 2; r++) {
            int e = tid + r*256;
            int k = e >> 4, n8 = (e & 15) * 8;
            cpa16(&sm.ld.B[buf][k][n8], &Bs[(long long)(kb + k)*ldb + colBase + n8]);
        }
        CPA_COMMIT();
    };

    const int NCH = 48;
    loadChunk(0, 0);
    for (int c = 0; c < NCH; c++) {
        int cb = c & 1;
        if (c + 1 < NCH) {
            loadChunk(c + 1, (c + 1) & 1);
            asm volatile("cp.async.wait_group 1;");
        } else {
            asm volatile("cp.async.wait_group 0;");
        }
        __syncthreads();
        #pragma unroll
        for (int ks = 0; ks < 32; ks += 16) {
            wmma::fragment<wmma::matrix_a, 16, 16, 16, __nv_bfloat16, wmma::row_major> af[2];
            wmma::fragment<wmma::matrix_b, 16, 16, 16, __nv_bfloat16, wmma::row_major> bf[4];
            #pragma unroll
            for (int i = 0; i < 2; i++)
                wmma::load_matrix_sync(af[i], &sm.ld.A[cb][wm*32 + i*16][ks], 48);
            #pragma unroll
            for (int j = 0; j < 4; j++)
                wmma::load_matrix_sync(bf[j], &sm.ld.B[cb][ks][wn*64 + j*16], 136);
            #pragma unroll
            for (int i = 0; i < 2; i++)
                #pragma unroll
                for (int j = 0; j < 4; j++)
                    wmma::mma_sync(acc[i][j], af[i], bf[j], acc[i][j]);
        }
        __syncthreads();
    }

    // epilogue in two 64-row halves through smem stage
    #pragma unroll
    for (int h = 0; h < 2; h++) {
        if (wm >= h*2 && wm < h*2 + 2) {
            #pragma unroll
            for (int i = 0; i < 2; i++)
                #pragma unroll
                for (int j = 0; j < 4; j++)
                    wmma::store_matrix_sync(&sm.st[(wm - h*2)*32 + i*16][wn*64 + j*16],
                                            acc[i][j], 132, wmma::mem_row_major);
        }
        __syncthreads();
        for (int e = tid; e < 64*128; e += 256) {
            int m = e >> 7, col = e & 127;
            int gc = colBase + col;
            if (gc < ncols) C[(long long)(h*64 + m)*ncols + gc] = sm.st[m][col];
        }
        __syncthreads();
    }
}

// ---- output projection: x[b, rowBase+m, DM+col] += relu(wo(512x128) @ pv[b](128x2688)) ----
// extended K = 3*128
__global__ __launch_bounds__(256)
void wmma_wo(const __nv_bfloat16* __restrict__ whi, const __nv_bfloat16* __restrict__ wlo,
             const __nv_bfloat16* __restrict__ phi, const __nv_bfloat16* __restrict__ plo,
             float* __restrict__ x)
{
    __shared__ SmemU sm;
    int tid = threadIdx.x;
    int rowBase = blockIdx.x * 128;
    int b = blockIdx.z;
    int colBase = blockIdx.y * 128;

    const __nv_bfloat16* Bhi = phi + (long long)b * (FF*OM);
    const __nv_bfloat16* Blo = plo + (long long)b * (FF*OM);

    const __nv_bfloat16* Asel[3] = {whi, whi, wlo};
    const __nv_bfloat16* Bsel[3] = {Bhi, Blo, Bhi};

    int warp = tid >> 5;
    int wm = warp & 3;
    int wn = warp >> 2;

    wmma::fragment<wmma::accumulator, 16, 16, 16, float> acc[2][4];
    #pragma unroll
    for (int i = 0; i < 2; i++)
        #pragma unroll
        for (int j = 0; j < 4; j++)
            wmma::fill_fragment(acc[i][j], 0.f);

    auto loadChunk = [&](int c, int buf) {
        int term = c >> 2;               // 4 chunks of 32 per term
        int kb = (c & 3) * 32;
        const __nv_bfloat16* As = Asel[term];
        const __nv_bfloat16* Bs = Bsel[term];
        #pragma unroll
        for (int r = 0; r < 2; r++) {
            int e = tid + r*256;
            int m = e >> 2, k8 = (e & 3) * 8;
            cpa16(&sm.ld.A[buf][m][k8], &As[(long long)(rowBase + m)*FF + kb + k8]);
        }
        #pragma unroll
        for (int r = 0; r < 2; r++) {
            int e = tid + r*256;
            int k = e >> 4, n8 = (e & 15) * 8;
            cpa16(&sm.ld.B[buf][k][n8], &Bs[(long long)(kb + k)*OM + colBase + n8]);
        }
        CPA_COMMIT();
    };

    const int NCH = 12;
    loadChunk(0, 0);
    for (int c = 0; c < NCH; c++) {
        int cb = c & 1;
        if (c + 1 < NCH) {
            loadChunk(c + 1, (c + 1) & 1);
            asm volatile("cp.async.wait_group 1;");
        } else {
            asm volatile("cp.async.wait_group 0;");
        }
        __syncthreads();
        #pragma unroll
        for (int ks = 0; ks < 32; ks += 16) {
            wmma::fragment<wmma::matrix_a, 16, 16, 16, __nv_bfloat16, wmma::row_major> af[2];
            wmma::fragment<wmma::matrix_b, 16, 16, 16, __nv_bfloat16, wmma::row_major> bf[4];
            #pragma unroll
            for (int i = 0; i < 2; i++)
                wmma::load_matrix_sync(af[i], &sm.ld.A[cb][wm*32 + i*16][ks], 48);
            #pragma unroll
            for (int j = 0; j < 4; j++)
                wmma::load_matrix_sync(bf[j], &sm.ld.B[cb][ks][wn*64 + j*16], 136);
            #pragma unroll
            for (int i = 0; i < 2; i++)
                #pragma unroll
                for (int j = 0; j < 4; j++)
                    wmma::mma_sync(acc[i][j], af[i], bf[j], acc[i][j]);
        }
        __syncthreads();
    }

    #pragma unroll
    for (int h = 0; h < 2; h++) {
        if (wm >= h*2 && wm < h*2 + 2) {
            #pragma unroll
            for (int i = 0; i < 2; i++)
                #pragma unroll
                for (int j = 0; j < 4; j++)
                    wmma::store_matrix_sync(&sm.st[(wm - h*2)*32 + i*16][wn*64 + j*16],
                                            acc[i][j], 132, wmma::mem_row_major);
        }
        __syncthreads();
        for (int e = tid; e < 64*128; e += 256) {
            int m = e >> 7, col = e & 127;
            long long xi = ((long long)(b*DD + rowBase + h*64 + m))*SPAT + DM + colBase + col;
            x[xi] += fmaxf(sm.st[m][col], 0.f);
        }
        __syncthreads();
    }
}

// ---------------- fused demo attention + dv_att ----------------
__global__ void demo_attn_kernel(const float* __restrict__ dk,
                                 const float* __restrict__ dq,
                                 const float* __restrict__ dv,
                                 float* __restrict__ dvatt)
{
    int i = blockIdx.x;      // 0..335
    int n = blockIdx.y;      // head
    int b = blockIdx.z;
    const long long base = ((long long)b*FF + n*CH) * DM;
    const float* Kp = dk + base;
    const float* Qp = dq + base;
    const float* Vp = dv + base;

    __shared__ float kv[CH];
    __shared__ float logit[DM];
    __shared__ float red[128];
    __shared__ float part[CH*128];
    int tid = threadIdx.x;

    if (tid < CH) kv[tid] = Kp[tid*DM + i];
    __syncthreads();

    int nvalid = (i / HWW + 1) * HWW;   // causal block mask

    float lmax = -1e30f;
    for (int j = tid; j < nvalid; j += 128) {
        float s = 0.f;
        #pragma unroll
        for (int c = 0; c < CH; c++) s += kv[c] * Qp[c*DM + j];
        s *= INV_TEMP;
        logit[j] = s;
        lmax = fmaxf(lmax, s);
    }
    red[tid] = lmax; __syncthreads();
    for (int o = 64; o > 0; o >>= 1) { if (tid < o) red[tid] = fmaxf(red[tid], red[tid+o]); __syncthreads(); }
    float m = red[0];
    __syncthreads();

    float lsum = 0.f;
    for (int j = tid; j < nvalid; j += 128) {
        float e = __expf(logit[j] - m);
        logit[j] = e;
        lsum += e;
    }
    red[tid] = lsum; __syncthreads();
    for (int o = 64; o > 0; o >>= 1) { if (tid < o) red[tid] += red[tid+o]; __syncthreads(); }
    float inv = 1.f / red[0];
    __syncthreads();

    float acc[CH] = {};
    for (int j = tid; j < nvalid; j += 128) {
        float p = logit[j];
        #pragma unroll
        for (int c = 0; c < CH; c++) acc[c] += p * Vp[c*DM + j];
    }
    #pragma unroll
    for (int c = 0; c < CH; c++) part[c*128 + tid] = acc[c];
    __syncthreads();
    for (int o = 64; o > 0; o >>= 1) {
        for (int idx = tid; idx < CH*o; idx += 128) {
            int c = idx / o, t = idx % o;
            part[c*128 + t] += part[c*128 + t + o];
        }
        __syncthreads();
    }
    if (tid < CH) dvatt[base + tid*DM + i] = part[tid*128] * inv;
}

// ---------------- fused obs attention per (b,t,n) ----------------
#define PCH 64
__global__ void obs_attn_kernel(const float* __restrict__ dk,
                                const float* __restrict__ dvatt,
                                const float* __restrict__ ok,
                                const float* __restrict__ ov,
                                const float* __restrict__ oq,
                                float* __restrict__ pv)
{
    int n = blockIdx.x, t = blockIdx.y, b = blockIdx.z;
    const long long obase = ((long long)b*FF + n*CH) * OM + (long long)t*HWW;
    const long long dbase = ((long long)b*FF + n*CH) * DM;

    __shared__ float qs[CH][HWW];     // 32x84
    __shared__ float ks[CH][PCH];     // 32x64
    __shared__ float vs[CH][PCH];
    __shared__ float S[PCH][HWW+1];   // 64x85

    int tid = threadIdx.x;
    int tx = tid % 16, ty = tid / 16;

    for (int l = tid; l < CH*HWW; l += 256) {
        int c = l / HWW, j = l % HWW;
        qs[c][j] = oq[obase + (long long)c*OM + j];
    }

    float acc[2][6] = {};

    for (int p0 = 0; p0 < CATP; p0 += PCH) {
        for (int l = tid; l < CH*PCH; l += 256) {
            int c = l / PCH, pl = l % PCH;
            int p = p0 + pl;
            float kk = 0.f, vv = 0.f;
            if (p < DM) {
                kk = dk   [dbase + (long long)c*DM + p];
                vv = dvatt[dbase + (long long)c*DM + p];
            } else if (p < CATP) {
                kk = ok[obase + (long long)c*OM + (p - DM)];
                vv = ov[obase + (long long)c*OM + (p - DM)];
            }
            ks[c][pl] = kk; vs[c][pl] = vv;
        }
        __syncthreads();

        {
            float sa[4][6] = {};
            #pragma unroll
            for (int k = 0; k < CH; k++) {
                float a[4], bq[6];
                #pragma unroll
                for (int pp = 0; pp < 4; pp++) a[pp] = ks[k][ty*4 + pp];
                #pragma unroll
                for (int jj = 0; jj < 6; jj++) {
                    int j = tx*6 + jj;
                    bq[jj] = (j < HWW) ? qs[k][j] : 0.f;
                }
                #pragma unroll
                for (int pp = 0; pp < 4; pp++)
                    #pragma unroll
                    for (int jj = 0; jj < 6; jj++)
                        sa[pp][jj] += a[pp] * bq[jj];
            }
            #pragma unroll
            for (int pp = 0; pp < 4; pp++)
                #pragma unroll
                for (int jj = 0; jj < 6; jj++) {
                    int j = tx*6 + jj;
                    if (j < HWW) S[ty*4 + pp][j] = sa[pp][jj] * INV_TEMP;
                }
        }
        __syncthreads();

        {
            int row = tid >> 2;
            int l4  = tid & 3;
            float mx = -1e30f;
            for (int j = l4; j < HWW; j += 4) mx = fmaxf(mx, S[row][j]);
            mx = fmaxf(mx, __shfl_xor_sync(0xffffffffu, mx, 1));
            mx = fmaxf(mx, __shfl_xor_sync(0xffffffffu, mx, 2));
            float sum = 0.f;
            for (int j = l4; j < HWW; j += 4) {
                float e = __expf(S[row][j] - mx);
                S[row][j] = e;
                sum += e;
            }
            sum += __shfl_xor_sync(0xffffffffu, sum, 1);
            sum += __shfl_xor_sync(0xffffffffu, sum, 2);
            float iv = 1.f / sum;
            bool valid = (p0 + row) < CATP;
            for (int j = l4; j < HWW; j += 4)
                S[row][j] = valid ? S[row][j] * iv : 0.f;
        }
        __syncthreads();

        #pragma unroll 4
        for (int pl = 0; pl < PCH; pl++) {
            float v0 = vs[ty][pl];
            float v1 = vs[ty+16][pl];
            float sv[6];
            #pragma unroll
            for (int jj = 0; jj < 6; jj++) {
                int i = tx*6 + jj;
                sv[jj] = (i < HWW) ? S[pl][i] : 0.f;
            }
            #pragma unroll
            for (int jj = 0; jj < 6; jj++) {
                acc[0][jj] += v0 * sv[jj];
                acc[1][jj] += v1 * sv[jj];
            }
        }
        __syncthreads();
    }

    #pragma unroll
    for (int cc = 0; cc < 2; cc++) {
        int c = ty + 16*cc;
        #pragma unroll
        for (int jj = 0; jj < 6; jj++) {
            int i = tx*6 + jj;
            if (i < HWW) pv[obase + (long long)c*OM + i] = acc[cc][jj];
        }
    }
}

// ---------------- batchnorm + optional fused bf16 hi/lo split of the output ----------------
__global__ void bn_kernel(const float* __restrict__ x, float* __restrict__ out,
                          const float* __restrict__ gamma, const float* __restrict__ beta,
                          __nv_bfloat16* __restrict__ hi, __nv_bfloat16* __restrict__ lo)
{
    int ch = blockIdx.x;
    int tid = threadIdx.x;
    const long long chOff = (long long)ch * SPAT;

    double s = 0.0, s2 = 0.0;
    for (int b = 0; b < BB; b++) {
        const float* p = x + (long long)b*DD*SPAT + chOff;
        for (int idx = tid; idx < SPAT; idx += 256) {
            float v = p[idx];
            s  += v;
            s2 += (double)v * v;
        }
    }
    __shared__ double rs[256], rs2[256];
    rs[tid] = s; rs2[tid] = s2; __syncthreads();
    for (int o = 128; o > 0; o >>= 1) {
        if (tid < o) { rs[tid] += rs[tid+o]; rs2[tid] += rs2[tid+o]; }
        __syncthreads();
    }
    const double cnt = (double)BB * SPAT;
    double mean = rs[0] / cnt;
    double var  = rs2[0] / cnt - mean*mean;
    float scale = (float)((double)gamma[ch] * rsqrt(var + 1e-5));
    float mn = (float)mean;
    float bt = beta[ch];
    for (int b = 0; b < BB; b++) {
        const long long off = (long long)b*DD*SPAT + chOff;
        const float* p = x + off;
        float*       q = out + off;
        for (int idx = tid; idx < SPAT; idx += 256) {
            float y = scale * (p[idx] - mn) + bt;
            q[idx] = y;
            if (hi) {
                __nv_bfloat16 h = __float2bfloat16(y);
                hi[off + idx] = h;
                lo[off + idx] = __float2bfloat16(y - __bfloat162float(h));
            }
        }
    }
}

// ---------------- host driver ----------------
extern "C" void kernel_launch(void* const* d_in, const int* in_sizes, int n_in,
                              void* d_out, int out_size)
{
    const float* inputs  = (const float*)d_in[0];
    const float* demo_wq = (const float*)d_in[1];
    const float* demo_wk = (const float*)d_in[2];
    const float* demo_wv = (const float*)d_in[3];
    // demo_wo (d_in[4]) unused by the reference
    const float* obs_wq  = (const float*)d_in[5];
    const float* obs_wk  = (const float*)d_in[6];
    const float* obs_wv  = (const float*)d_in[7];
    const float* obs_wo  = (const float*)d_in[8];
    const float* bn_g    = (const float*)d_in[9];
    const float* bn_b    = (const float*)d_in[10];
    float* out = (float*)d_out;

    float *xp, *dqp, *dkp, *dvp, *dvattp, *oqp, *okp, *ovp, *pvp;
    __nv_bfloat16 *xhip, *xlop, *pvhip, *pvlop, *wqhip, *wqlop, *wohip, *wolop;
    cudaGetSymbolAddress((void**)&xp,     g_x);
    cudaGetSymbolAddress((void**)&dqp,    g_dq);
    cudaGetSymbolAddress((void**)&dkp,    g_dk);
    cudaGetSymbolAddress((void**)&dvp,    g_dv);
    cudaGetSymbolAddress((void**)&dvattp, g_dvatt);
    cudaGetSymbolAddress((void**)&oqp,    g_oq);
    cudaGetSymbolAddress((void**)&okp,    g_ok);
    cudaGetSymbolAddress((void**)&ovp,    g_ov);
    cudaGetSymbolAddress((void**)&pvp,    g_pv);
    cudaGetSymbolAddress((void**)&xhip,   g_xhi);
    cudaGetSymbolAddress((void**)&xlop,   g_xlo);
    cudaGetSymbolAddress((void**)&pvhip,  g_pvhi);
    cudaGetSymbolAddress((void**)&pvlop,  g_pvlo);
    cudaGetSymbolAddress((void**)&wqhip,  g_wqhi);
    cudaGetSymbolAddress((void**)&wqlop,  g_wqlo);
    cudaGetSymbolAddress((void**)&wohip,  g_wohi);
    cudaGetSymbolAddress((void**)&wolop,  g_wolo);

    cudaMemcpyAsync(xp, inputs, (size_t)BB*DD*SPAT*sizeof(float),
                    cudaMemcpyDeviceToDevice, 0);

    // convert weights: [tensor][layer][FF*DD]
    const int WT = 2*FF*DD;   // per-tensor element count (both layers)
    const float* wsrc[6] = {demo_wq, demo_wk, demo_wv, obs_wq, obs_wk, obs_wv};
    for (int t = 0; t < 6; t++)
        cvt_pair<<<WT/256, 256>>>(wsrc[t], wqhip + (long long)t*WT, wqlop + (long long)t*WT, WT);
    cvt_pair<<<WT/256, 256>>>(obs_wo, wohip, wolop, WT);

    const long long XEL = (long long)BB*DD*SPAT;
    const long long PEL = (long long)BB*FF*OM;
    const long long XB  = (long long)DD*SPAT;
    const long long QD  = (long long)FF*DM;
    const long long QO  = (long long)FF*OM;

    // initial bf16 split of x (layer 1's split is fused into bn_kernel)
    cvt_pair<<<(unsigned)((XEL + 255)/256), 256>>>(xp, xhip, xlop, (int)XEL);

    for (int i = 0; i < 2; i++) {
        const long long lw = (long long)i*FF*DD;

        // demo QKV (tensor cores): grid (3 weights, 3 col tiles, 8 batches)
        wmma_qkv<<<dim3(3, (DM + 127)/128, BB), 256>>>(
            wqhip + lw, wqlop + lw, xhip, xlop,
            dqp, dkp, dvp, DM, SPAT, XB, QD);

        demo_attn_kernel<<<dim3(DM, NH, BB), 128>>>(dkp, dqp, dvp, dvattp);

        // obs QKV: weights 3..5, x offset DM
        wmma_qkv<<<dim3(3, OM/128, BB), 256>>>(
            wqhip + 3LL*WT + lw, wqlop + 3LL*WT + lw, xhip + DM, xlop + DM,
            oqp, okp, ovp, OM, SPAT, XB, QO);

        obs_attn_kernel<<<dim3(NH, OBS_TT, BB), 256>>>(dkp, dvattp, okp, ovp, oqp, pvp);

        // split pv, then output projection + residual + relu into x
        cvt_pair<<<(unsigned)((PEL + 255)/256), 256>>>(pvp, pvhip, pvlop, (int)PEL);
        wmma_wo<<<dim3(DD/128, OM/128, BB), 256>>>(
            wohip + lw, wolop + lw, pvhip, pvlop, xp);

        // batchnorm; layer 0 also emits next layer's bf16 split
        bn_kernel<<<DD, 256>>>(xp, (i == 1) ? out : xp, bn_g + i*DD, bn_b + i*DD,
                               (i == 0) ? xhip : (__nv_bfloat16*)nullptr,
                               (i == 0) ? xlop : (__nv_bfloat16*)nullptr);
    }
}

// round 8
// speedup vs baseline: 1.1486x; 1.0328x over previous
#include <cuda_runtime.h>
#include <cuda_bf16.h>
#include <mma.h>
#include <cstdint>

using namespace nvcuda;

// ---------------- problem constants ----------------
#define BB 8
#define DD 512
#define T_TOT 36
#define DEMO_TT 4
#define OBS_TT 32
#define HWW 84
#define FF 128
#define NH 4
#define CH 32               // channels per head
#define DM (DEMO_TT*HWW)    // 336 demo positions
#define OM (OBS_TT*HWW)     // 2688 obs positions
#define CATP (DM+HWW)       // 420 concat positions
#define SPAT (T_TOT*HWW)    // 3024

static constexpr float INV_TEMP = 0.044194173824159216f; // 1/sqrt(512)

// ---------------- device scratch (no cudaMalloc allowed) ----------------
__device__ float g_x    [BB*DD*SPAT];    // running activation (B,512,36,84)
__device__ float g_dq   [BB*FF*DM];
__device__ float g_dk   [BB*FF*DM];
__device__ float g_dv   [BB*FF*DM];
__device__ float g_dvatt[BB*FF*DM];
__device__ float g_oq   [BB*FF*OM];
__device__ float g_ok   [BB*FF*OM];
__device__ float g_ov   [BB*FF*OM];

// bf16 hi/lo split operands for tensor-core GEMMs
__device__ __nv_bfloat16 g_xhi [BB*DD*SPAT];
__device__ __nv_bfloat16 g_xlo [BB*DD*SPAT];
__device__ __nv_bfloat16 g_pvhi[BB*FF*OM];
__device__ __nv_bfloat16 g_pvlo[BB*FF*OM];
// packed qkv weights: [tensor 0..5][layer 0..1][FF*DD], tensors: dq,dk,dv,oq,ok,ov
__device__ __nv_bfloat16 g_wqhi[6*2*FF*DD];
__device__ __nv_bfloat16 g_wqlo[6*2*FF*DD];
__device__ __nv_bfloat16 g_wohi[2*DD*FF];
__device__ __nv_bfloat16 g_wolo[2*DD*FF];

// ---------------- cp.async helpers (sm_80+ baseline features) ----------------
__device__ __forceinline__ void cpa16(void* dst_smem, const void* src) {
    uint32_t d = (uint32_t)__cvta_generic_to_shared(dst_smem);
    asm volatile("cp.async.cg.shared.global [%0], [%1], 16;" :: "r"(d), "l"(src));
}
#define CPA_COMMIT() asm volatile("cp.async.commit_group;")

// ---------------- fp32 -> bf16 hi/lo split ----------------
__global__ void cvt_pair(const float* __restrict__ s, __nv_bfloat16* __restrict__ hi,
                         __nv_bfloat16* __restrict__ lo, int n)
{
    int i = blockIdx.x * 256 + threadIdx.x;
    if (i < n) {
        float v = s[i];
        __nv_bfloat16 h = __float2bfloat16(v);
        hi[i] = h;
        lo[i] = __float2bfloat16(v - __bfloat162float(h));
    }
}

// all 7 weight tensors in one launch: blockIdx.y = tensor id (0..5 qkv, 6 = wo)
__global__ void cvt_weights(const float* s0, const float* s1, const float* s2,
                            const float* s3, const float* s4, const float* s5,
                            const float* s6,
                            __nv_bfloat16* __restrict__ qhi, __nv_bfloat16* __restrict__ qlo,
                            __nv_bfloat16* __restrict__ ohi, __nv_bfloat16* __restrict__ olo,
                            int n)
{
    int t = blockIdx.y;
    const float* s = (t==0)?s0:(t==1)?s1:(t==2)?s2:(t==3)?s3:(t==4)?s4:(t==5)?s5:s6;
    __nv_bfloat16* hi = (t < 6) ? qhi + (long long)t*n : ohi;
    __nv_bfloat16* lo = (t < 6) ? qlo + (long long)t*n : olo;
    int i = blockIdx.x * 256 + threadIdx.x;
    if (i < n) {
        float v = s[i];
        __nv_bfloat16 h = __float2bfloat16(v);
        hi[i] = h;
        lo[i] = __float2bfloat16(v - __bfloat162float(h));
    }
}

// ================= WMMA GEMM (128x128 tile, bf16 HMMA, fp32 accum) =================
union SmemU {
    struct { __nv_bfloat16 A[2][128][48]; __nv_bfloat16 B[2][32][136]; } ld;
    float st[64][132];
};

// ---------------- QKV GEMM: C_w[b](128 x ncols) = W_w(128x512) * X[b](512 x ncols) ----
__global__ __launch_bounds__(256)
void wmma_qkv(const __nv_bfloat16* __restrict__ whi, const __nv_bfloat16* __restrict__ wlo,
              const __nv_bfloat16* __restrict__ xhi, const __nv_bfloat16* __restrict__ xlo,
              float* __restrict__ Cq, float* __restrict__ Ck, float* __restrict__ Cv,
              int ncols, int ldb, long long bStride, long long cStride)
{
    __shared__ SmemU sm;
    int tid = threadIdx.x;
    int w = blockIdx.x;
    int b = blockIdx.z;
    int colBase = blockIdx.y * 128;

    const __nv_bfloat16* Ahi = whi + (long long)w * (2*FF*DD);
    const __nv_bfloat16* Alo = wlo + (long long)w * (2*FF*DD);
    const __nv_bfloat16* Bhi = xhi + (long long)b * bStride;
    const __nv_bfloat16* Blo = xlo + (long long)b * bStride;
    float* C = ((w == 0) ? Cq : (w == 1) ? Ck : Cv) + (long long)b * cStride;

    const __nv_bfloat16* Asel[3] = {Ahi, Ahi, Alo};
    const __nv_bfloat16* Bsel[3] = {Bhi, Blo, Bhi};

    int warp = tid >> 5;
    int wm = warp & 3;
    int wn = warp >> 2;

    wmma::fragment<wmma::accumulator, 16, 16, 16, float> acc[2][4];
    #pragma unroll
    for (int i = 0; i < 2; i++)
        #pragma unroll
        for (int j = 0; j < 4; j++)
            wmma::fill_fragment(acc[i][j], 0.f);

    auto loadChunk = [&](int c, int buf) {
        int term = c >> 4;
        int kb = (c & 15) * 32;
        const __nv_bfloat16* As = Asel[term];
        const __nv_bfloat16* Bs = Bsel[term];
        #pragma unroll
        for (int r = 0; r < 2; r++) {
            int e = tid + r*256;
            int m = e >> 2, k8 = (e & 3) * 8;
            cpa16(&sm.ld.A[buf][m][k8], &As[(long long)m*DD + kb + k8]);
        }
        #pragma unroll
        for (int r = 0; r < 2; r++) {
            int e = tid + r*256;
            int k = e >> 4, n8 = (e & 15) * 8;
            cpa16(&sm.ld.B[buf][k][n8], &Bs[(long long)(kb + k)*ldb + colBase + n8]);
        }
        CPA_COMMIT();
    };

    const int NCH = 48;
    loadChunk(0, 0);
    for (int c = 0; c < NCH; c++) {
        int cb = c & 1;
        if (c + 1 < NCH) {
            loadChunk(c + 1, (c + 1) & 1);
            asm volatile("cp.async.wait_group 1;");
        } else {
            asm volatile("cp.async.wait_group 0;");
        }
        __syncthreads();
        #pragma unroll
        for (int ks = 0; ks < 32; ks += 16) {
            wmma::fragment<wmma::matrix_a, 16, 16, 16, __nv_bfloat16, wmma::row_major> af[2];
            wmma::fragment<wmma::matrix_b, 16, 16, 16, __nv_bfloat16, wmma::row_major> bf[4];
            #pragma unroll
            for (int i = 0; i < 2; i++)
                wmma::load_matrix_sync(af[i], &sm.ld.A[cb][wm*32 + i*16][ks], 48);
            #pragma unroll
            for (int j = 0; j < 4; j++)
                wmma::load_matrix_sync(bf[j], &sm.ld.B[cb][ks][wn*64 + j*16], 136);
            #pragma unroll
            for (int i = 0; i < 2; i++)
                #pragma unroll
                for (int j = 0; j < 4; j++)
                    wmma::mma_sync(acc[i][j], af[i], bf[j], acc[i][j]);
        }
        __syncthreads();
    }

    #pragma unroll
    for (int h = 0; h < 2; h++) {
        if (wm >= h*2 && wm < h*2 + 2) {
            #pragma unroll
            for (int i = 0; i < 2; i++)
                #pragma unroll
                for (int j = 0; j < 4; j++)
                    wmma::store_matrix_sync(&sm.st[(wm - h*2)*32 + i*16][wn*64 + j*16],
                                            acc[i][j], 132, wmma::mem_row_major);
        }
        __syncthreads();
        for (int e = tid; e < 64*128; e += 256) {
            int m = e >> 7, col = e & 127;
            int gc = colBase + col;
            if (gc < ncols) C[(long long)(h*64 + m)*ncols + gc] = sm.st[m][col];
        }
        __syncthreads();
    }
}

// ---- output projection: x[b, rowBase+m, DM+col] += relu(wo(512x128) @ pv[b](128x2688)) ----
__global__ __launch_bounds__(256)
void wmma_wo(const __nv_bfloat16* __restrict__ whi, const __nv_bfloat16* __restrict__ wlo,
             const __nv_bfloat16* __restrict__ phi, const __nv_bfloat16* __restrict__ plo,
             float* __restrict__ x)
{
    __shared__ SmemU sm;
    int tid = threadIdx.x;
    int rowBase = blockIdx.x * 128;
    int b = blockIdx.z;
    int colBase = blockIdx.y * 128;

    const __nv_bfloat16* Bhi = phi + (long long)b * (FF*OM);
    const __nv_bfloat16* Blo = plo + (long long)b * (FF*OM);

    const __nv_bfloat16* Asel[3] = {whi, whi, wlo};
    const __nv_bfloat16* Bsel[3] = {Bhi, Blo, Bhi};

    int warp = tid >> 5;
    int wm = warp & 3;
    int wn = warp >> 2;

    wmma::fragment<wmma::accumulator, 16, 16, 16, float> acc[2][4];
    #pragma unroll
    for (int i = 0; i < 2; i++)
        #pragma unroll
        for (int j = 0; j < 4; j++)
            wmma::fill_fragment(acc[i][j], 0.f);

    auto loadChunk = [&](int c, int buf) {
        int term = c >> 2;
        int kb = (c & 3) * 32;
        const __nv_bfloat16* As = Asel[term];
        const __nv_bfloat16* Bs = Bsel[term];
        #pragma unroll
        for (int r = 0; r < 2; r++) {
            int e = tid + r*256;
            int m = e >> 2, k8 = (e & 3) * 8;
            cpa16(&sm.ld.A[buf][m][k8], &As[(long long)(rowBase + m)*FF + kb + k8]);
        }
        #pragma unroll
        for (int r = 0; r < 2; r++) {
            int e = tid + r*256;
            int k = e >> 4, n8 = (e & 15) * 8;
            cpa16(&sm.ld.B[buf][k][n8], &Bs[(long long)(kb + k)*OM + colBase + n8]);
        }
        CPA_COMMIT();
    };

    const int NCH = 12;
    loadChunk(0, 0);
    for (int c = 0; c < NCH; c++) {
        int cb = c & 1;
        if (c + 1 < NCH) {
            loadChunk(c + 1, (c + 1) & 1);
            asm volatile("cp.async.wait_group 1;");
        } else {
            asm volatile("cp.async.wait_group 0;");
        }
        __syncthreads();
        #pragma unroll
        for (int ks = 0; ks < 32; ks += 16) {
            wmma::fragment<wmma::matrix_a, 16, 16, 16, __nv_bfloat16, wmma::row_major> af[2];
            wmma::fragment<wmma::matrix_b, 16, 16, 16, __nv_bfloat16, wmma::row_major> bf[4];
            #pragma unroll
            for (int i = 0; i < 2; i++)
                wmma::load_matrix_sync(af[i], &sm.ld.A[cb][wm*32 + i*16][ks], 48);
            #pragma unroll
            for (int j = 0; j < 4; j++)
                wmma::load_matrix_sync(bf[j], &sm.ld.B[cb][ks][wn*64 + j*16], 136);
            #pragma unroll
            for (int i = 0; i < 2; i++)
                #pragma unroll
                for (int j = 0; j < 4; j++)
                    wmma::mma_sync(acc[i][j], af[i], bf[j], acc[i][j]);
        }
        __syncthreads();
    }

    #pragma unroll
    for (int h = 0; h < 2; h++) {
        if (wm >= h*2 && wm < h*2 + 2) {
            #pragma unroll
            for (int i = 0; i < 2; i++)
                #pragma unroll
                for (int j = 0; j < 4; j++)
                    wmma::store_matrix_sync(&sm.st[(wm - h*2)*32 + i*16][wn*64 + j*16],
                                            acc[i][j], 132, wmma::mem_row_major);
        }
        __syncthreads();
        for (int e = tid; e < 64*128; e += 256) {
            int m = e >> 7, col = e & 127;
            long long xi = ((long long)(b*DD + rowBase + h*64 + m))*SPAT + DM + colBase + col;
            x[xi] += fmaxf(sm.st[m][col], 0.f);
        }
        __syncthreads();
    }
}

// ---------------- fused demo attention + dv_att ----------------
__global__ void demo_attn_kernel(const float* __restrict__ dk,
                                 const float* __restrict__ dq,
                                 const float* __restrict__ dv,
                                 float* __restrict__ dvatt)
{
    int i = blockIdx.x;
    int n = blockIdx.y;
    int b = blockIdx.z;
    const long long base = ((long long)b*FF + n*CH) * DM;
    const float* Kp = dk + base;
    const float* Qp = dq + base;
    const float* Vp = dv + base;

    __shared__ float kv[CH];
    __shared__ float logit[DM];
    __shared__ float red[128];
    __shared__ float part[CH*128];
    int tid = threadIdx.x;

    if (tid < CH) kv[tid] = Kp[tid*DM + i];
    __syncthreads();

    int nvalid = (i / HWW + 1) * HWW;   // causal block mask

    float lmax = -1e30f;
    for (int j = tid; j < nvalid; j += 128) {
        float s = 0.f;
        #pragma unroll
        for (int c = 0; c < CH; c++) s += kv[c] * Qp[c*DM + j];
        s *= INV_TEMP;
        logit[j] = s;
        lmax = fmaxf(lmax, s);
    }
    red[tid] = lmax; __syncthreads();
    for (int o = 64; o > 0; o >>= 1) { if (tid < o) red[tid] = fmaxf(red[tid], red[tid+o]); __syncthreads(); }
    float m = red[0];
    __syncthreads();

    float lsum = 0.f;
    for (int j = tid; j < nvalid; j += 128) {
        float e = __expf(logit[j] - m);
        logit[j] = e;
        lsum += e;
    }
    red[tid] = lsum; __syncthreads();
    for (int o = 64; o > 0; o >>= 1) { if (tid < o) red[tid] += red[tid+o]; __syncthreads(); }
    float inv = 1.f / red[0];
    __syncthreads();

    float acc[CH] = {};
    for (int j = tid; j < nvalid; j += 128) {
        float p = logit[j];
        #pragma unroll
        for (int c = 0; c < CH; c++) acc[c] += p * Vp[c*DM + j];
    }
    #pragma unroll
    for (int c = 0; c < CH; c++) part[c*128 + tid] = acc[c];
    __syncthreads();
    for (int o = 64; o > 0; o >>= 1) {
        for (int idx = tid; idx < CH*o; idx += 128) {
            int c = idx / o, t = idx % o;
            part[c*128 + t] += part[c*128 + t + o];
        }
        __syncthreads();
    }
    if (tid < CH) dvatt[base + tid*DM + i] = part[tid*128] * inv;
}

// ---------------- fused obs attention per (b,t,n) ----------------
// Writes pv directly as bf16 hi/lo (feeds wmma_wo).
#define PCH 64
__global__ __launch_bounds__(256)
void obs_attn_kernel(const float* __restrict__ dk,
                     const float* __restrict__ dvatt,
                     const float* __restrict__ ok,
                     const float* __restrict__ ov,
                     const float* __restrict__ oq,
                     __nv_bfloat16* __restrict__ pvhi,
                     __nv_bfloat16* __restrict__ pvlo)
{
    int n = blockIdx.x, t = blockIdx.y, b = blockIdx.z;
    const long long obase = ((long long)b*FF + n*CH) * OM + (long long)t*HWW;
    const long long dbase = ((long long)b*FF + n*CH) * DM;

    __shared__ float qs[CH][HWW];     // 32x84
    __shared__ float ks[CH][PCH];     // 32x64
    __shared__ float vs[CH][PCH];     // 32x64, rows 16B-aligned (PCH*4=256B)
    __shared__ float S[PCH][HWW+1];   // 64x85

    int tid = threadIdx.x;
    int tx = tid % 16, ty = tid / 16;
    int warp = tid >> 5, lane = tid & 31;
    int c0 = warp * 4;                // 8 warps x 4 channels = 32

    for (int l = tid; l < CH*HWW; l += 256) {
        int c = l / HWW, j = l % HWW;
        qs[c][j] = oq[obase + (long long)c*OM + j];
    }

    // PV accumulators: warp owns channels c0..c0+3; lane owns j = lane, lane+32, lane+64
    float acc[4][3] = {};

    for (int p0 = 0; p0 < CATP; p0 += PCH) {
        for (int l = tid; l < CH*PCH; l += 256) {
            int c = l / PCH, pl = l % PCH;
            int p = p0 + pl;
            float kk = 0.f, vv = 0.f;
            if (p < DM) {
                kk = dk   [dbase + (long long)c*DM + p];
                vv = dvatt[dbase + (long long)c*DM + p];
            } else if (p < CATP) {
                kk = ok[obase + (long long)c*OM + (p - DM)];
                vv = ov[obase + (long long)c*OM + (p - DM)];
            }
            ks[c][pl] = kk; vs[c][pl] = vv;
        }
        __syncthreads();

        // logits: rows p = ty*4+pp, cols j = tx*6+jj
        {
            float sa[4][6] = {};
            #pragma unroll
            for (int k = 0; k < CH; k++) {
                float a[4], bq[6];
                #pragma unroll
                for (int pp = 0; pp < 4; pp++) a[pp] = ks[k][ty*4 + pp];
                #pragma unroll
                for (int jj = 0; jj < 6; jj++) {
                    int j = tx*6 + jj;
                    bq[jj] = (j < HWW) ? qs[k][j] : 0.f;
                }
                #pragma unroll
                for (int pp = 0; pp < 4; pp++)
                    #pragma unroll
                    for (int jj = 0; jj < 6; jj++)
                        sa[pp][jj] += a[pp] * bq[jj];
            }
            #pragma unroll
            for (int pp = 0; pp < 4; pp++)
                #pragma unroll
                for (int jj = 0; jj < 6; jj++) {
                    int j = tx*6 + jj;
                    if (j < HWW) S[ty*4 + pp][j] = sa[pp][jj] * INV_TEMP;
                }
        }
        __syncthreads();

        // parallel softmax: 4 threads per row, shfl reductions
        {
            int row = tid >> 2;
            int l4  = tid & 3;
            float mx = -1e30f;
            for (int j = l4; j < HWW; j += 4) mx = fmaxf(mx, S[row][j]);
            mx = fmaxf(mx, __shfl_xor_sync(0xffffffffu, mx, 1));
            mx = fmaxf(mx, __shfl_xor_sync(0xffffffffu, mx, 2));
            float sum = 0.f;
            for (int j = l4; j < HWW; j += 4) {
                float e = __expf(S[row][j] - mx);
                S[row][j] = e;
                sum += e;
            }
            sum += __shfl_xor_sync(0xffffffffu, sum, 1);
            sum += __shfl_xor_sync(0xffffffffu, sum, 2);
            float iv = 1.f / sum;
            bool valid = (p0 + row) < CATP;
            for (int j = l4; j < HWW; j += 4)
                S[row][j] = valid ? S[row][j] * iv : 0.f;
        }
        __syncthreads();

        // PV accumulate: pl unrolled x4, vs read as float4 (broadcast LDS.128)
        #pragma unroll 2
        for (int pl = 0; pl < PCH; pl += 4) {
            float4 v[4];
            #pragma unroll
            for (int cc = 0; cc < 4; cc++)
                v[cc] = *(const float4*)&vs[c0 + cc][pl];
            #pragma unroll
            for (int q = 0; q < 4; q++) {
                float s0 = S[pl + q][lane];
                float s1 = S[pl + q][lane + 32];
                float s2 = (lane < HWW - 64) ? S[pl + q][lane + 64] : 0.f;
                #pragma unroll
                for (int cc = 0; cc < 4; cc++) {
                    float vq = (q == 0) ? v[cc].x : (q == 1) ? v[cc].y
                             : (q == 2) ? v[cc].z : v[cc].w;
                    acc[cc][0] += vq * s0;
                    acc[cc][1] += vq * s1;
                    acc[cc][2] += vq * s2;
                }
            }
        }
        __syncthreads();
    }

    // write pv directly as bf16 hi/lo
    #pragma unroll
    for (int cc = 0; cc < 4; cc++) {
        long long o = obase + (long long)(c0 + cc)*OM;
        #pragma unroll
        for (int r = 0; r < 3; r++) {
            int j = lane + r*32;
            if (j < HWW) {
                float vv = acc[cc][r];
                __nv_bfloat16 h = __float2bfloat16(vv);
                pvhi[o + j] = h;
                pvlo[o + j] = __float2bfloat16(vv - __bfloat162float(h));
            }
        }
    }
}

// ---------------- batchnorm + optional fused bf16 hi/lo split of the output ----------------
__global__ void bn_kernel(const float* __restrict__ x, float* __restrict__ out,
                          const float* __restrict__ gamma, const float* __restrict__ beta,
                          __nv_bfloat16* __restrict__ hi, __nv_bfloat16* __restrict__ lo)
{
    int ch = blockIdx.x;
    int tid = threadIdx.x;
    const long long chOff = (long long)ch * SPAT;

    double s = 0.0, s2 = 0.0;
    for (int b = 0; b < BB; b++) {
        const float* p = x + (long long)b*DD*SPAT + chOff;
        for (int idx = tid; idx < SPAT; idx += 256) {
            float v = p[idx];
            s  += v;
            s2 += (double)v * v;
        }
    }
    __shared__ double rs[256], rs2[256];
    rs[tid] = s; rs2[tid] = s2; __syncthreads();
    for (int o = 128; o > 0; o >>= 1) {
        if (tid < o) { rs[tid] += rs[tid+o]; rs2[tid] += rs2[tid+o]; }
        __syncthreads();
    }
    const double cnt = (double)BB * SPAT;
    double mean = rs[0] / cnt;
    double var  = rs2[0] / cnt - mean*mean;
    float scale = (float)((double)gamma[ch] * rsqrt(var + 1e-5));
    float mn = (float)mean;
    float bt = beta[ch];
    for (int b = 0; b < BB; b++) {
        const long long off = (long long)b*DD*SPAT + chOff;
        const float* p = x + off;
        float*       q = out + off;
        for (int idx = tid; idx < SPAT; idx += 256) {
            float y = scale * (p[idx] - mn) + bt;
            q[idx] = y;
            if (hi) {
                __nv_bfloat16 h = __float2bfloat16(y);
                hi[off + idx] = h;
                lo[off + idx] = __float2bfloat16(y - __bfloat162float(h));
            }
        }
    }
}

// ---------------- host driver ----------------
extern "C" void kernel_launch(void* const* d_in, const int* in_sizes, int n_in,
                              void* d_out, int out_size)
{
    const float* inputs  = (const float*)d_in[0];
    const float* demo_wq = (const float*)d_in[1];
    const float* demo_wk = (const float*)d_in[2];
    const float* demo_wv = (const float*)d_in[3];
    // demo_wo (d_in[4]) unused by the reference
    const float* obs_wq  = (const float*)d_in[5];
    const float* obs_wk  = (const float*)d_in[6];
    const float* obs_wv  = (const float*)d_in[7];
    const float* obs_wo  = (const float*)d_in[8];
    const float* bn_g    = (const float*)d_in[9];
    const float* bn_b    = (const float*)d_in[10];
    float* out = (float*)d_out;

    float *xp, *dqp, *dkp, *dvp, *dvattp, *oqp, *okp, *ovp;
    __nv_bfloat16 *xhip, *xlop, *pvhip, *pvlop, *wqhip, *wqlop, *wohip, *wolop;
    cudaGetSymbolAddress((void**)&xp,     g_x);
    cudaGetSymbolAddress((void**)&dqp,    g_dq);
    cudaGetSymbolAddress((void**)&dkp,    g_dk);
    cudaGetSymbolAddress((void**)&dvp,    g_dv);
    cudaGetSymbolAddress((void**)&dvattp, g_dvatt);
    cudaGetSymbolAddress((void**)&oqp,    g_oq);
    cudaGetSymbolAddress((void**)&okp,    g_ok);
    cudaGetSymbolAddress((void**)&ovp,    g_ov);
    cudaGetSymbolAddress((void**)&xhip,   g_xhi);
    cudaGetSymbolAddress((void**)&xlop,   g_xlo);
    cudaGetSymbolAddress((void**)&pvhip,  g_pvhi);
    cudaGetSymbolAddress((void**)&pvlop,  g_pvlo);
    cudaGetSymbolAddress((void**)&wqhip,  g_wqhi);
    cudaGetSymbolAddress((void**)&wqlop,  g_wqlo);
    cudaGetSymbolAddress((void**)&wohip,  g_wohi);
    cudaGetSymbolAddress((void**)&wolop,  g_wolo);

    cudaMemcpyAsync(xp, inputs, (size_t)BB*DD*SPAT*sizeof(float),
                    cudaMemcpyDeviceToDevice, 0);

    // convert all 7 weight tensors in one launch
    const int WT = 2*FF*DD;
    cvt_weights<<<dim3(WT/256, 7), 256>>>(demo_wq, demo_wk, demo_wv,
                                          obs_wq, obs_wk, obs_wv, obs_wo,
                                          wqhip, wqlop, wohip, wolop, WT);

    const long long XEL = (long long)BB*DD*SPAT;
    const long long XB  = (long long)DD*SPAT;
    const long long QD  = (long long)FF*DM;
    const long long QO  = (long long)FF*OM;

    // initial bf16 split of x (layer 1's split is fused into bn_kernel)
    cvt_pair<<<(unsigned)((XEL + 255)/256), 256>>>(xp, xhip, xlop, (int)XEL);

    for (int i = 0; i < 2; i++) {
        const long long lw = (long long)i*FF*DD;

        // demo QKV (tensor cores)
        wmma_qkv<<<dim3(3, (DM + 127)/128, BB), 256>>>(
            wqhip + lw, wqlop + lw, xhip, xlop,
            dqp, dkp, dvp, DM, SPAT, XB, QD);

        demo_attn_kernel<<<dim3(DM, NH, BB), 128>>>(dkp, dqp, dvp, dvattp);

        // obs QKV
        wmma_qkv<<<dim3(3, OM/128, BB), 256>>>(
            wqhip + 3LL*WT + lw, wqlop + 3LL*WT + lw, xhip + DM, xlop + DM,
            oqp, okp, ovp, OM, SPAT, XB, QO);

        // obs attention -> pv bf16 hi/lo directly
        obs_attn_kernel<<<dim3(NH, OBS_TT, BB), 256>>>(dkp, dvattp, okp, ovp, oqp,
                                                       pvhip, pvlop);

        // output projection + residual + relu into x
        wmma_wo<<<dim3(DD/128, OM/128, BB), 256>>>(
            wohip + lw, wolop + lw, pvhip, pvlop, xp);

        // batchnorm; layer 0 also emits next layer's bf16 split
        bn_kernel<<<DD, 256>>>(xp, (i == 1) ? out : xp, bn_g + i*DD, bn_b + i*DD,
                               (i == 0) ? xhip : (__nv_bfloat16*)nullptr,
                               (i == 0) ? xlop : (__nv_bfloat16*)nullptr);
    }
}

// round 12
// speedup vs baseline: 1.2650x; 1.1013x over previous
#include <cuda_runtime.h>
#include <cuda_bf16.h>
#include <mma.h>
#include <cstdint>

using namespace nvcuda;

// ---------------- problem constants ----------------
#define BB 8
#define DD 512
#define T_TOT 36
#define DEMO_TT 4
#define OBS_TT 32
#define HWW 84
#define FF 128
#define NH 4
#define CH 32               // channels per head
#define DM (DEMO_TT*HWW)    // 336 demo positions
#define OM (OBS_TT*HWW)     // 2688 obs positions
#define CATP (DM+HWW)       // 420 concat positions
#define SPAT (T_TOT*HWW)    // 3024

static constexpr float INV_TEMP = 0.044194173824159216f; // 1/sqrt(512)

// ---------------- device scratch (no cudaMalloc allowed) ----------------
__device__ float g_x    [BB*DD*SPAT];    // running activation (B,512,36,84)
__device__ float g_dq   [BB*FF*DM];
__device__ float g_dk   [BB*FF*DM];
__device__ float g_dv   [BB*FF*DM];
__device__ float g_dvatt[BB*FF*DM];
__device__ float g_oq   [BB*FF*OM];
__device__ float g_ok   [BB*FF*OM];
__device__ float g_ov   [BB*FF*OM];

// bf16 hi/lo split operands for tensor-core GEMMs
__device__ __nv_bfloat16 g_xhi [BB*DD*SPAT];
__device__ __nv_bfloat16 g_xlo [BB*DD*SPAT];
__device__ __nv_bfloat16 g_pvhi[BB*FF*OM];
__device__ __nv_bfloat16 g_pvlo[BB*FF*OM];
// packed qkv weights: [tensor 0..5][layer 0..1][FF*DD], tensors: dq,dk,dv,oq,ok,ov
__device__ __nv_bfloat16 g_wqhi[6*2*FF*DD];
__device__ __nv_bfloat16 g_wqlo[6*2*FF*DD];
__device__ __nv_bfloat16 g_wohi[2*DD*FF];
__device__ __nv_bfloat16 g_wolo[2*DD*FF];

// ---------------- cp.async helpers (sm_80+ baseline features) ----------------
__device__ __forceinline__ void cpa16(void* dst_smem, const void* src) {
    uint32_t d = (uint32_t)__cvta_generic_to_shared(dst_smem);
    asm volatile("cp.async.cg.shared.global [%0], [%1], 16;" :: "r"(d), "l"(src));
}
#define CPA_COMMIT() asm volatile("cp.async.commit_group;")

// ---------------- fp32 -> bf16 hi/lo split ----------------
__global__ void cvt_pair(const float* __restrict__ s, __nv_bfloat16* __restrict__ hi,
                         __nv_bfloat16* __restrict__ lo, int n)
{
    int i = blockIdx.x * 256 + threadIdx.x;
    if (i < n) {
        float v = s[i];
        __nv_bfloat16 h = __float2bfloat16(v);
        hi[i] = h;
        lo[i] = __float2bfloat16(v - __bfloat162float(h));
    }
}

// all 7 weight tensors in one launch: blockIdx.y = tensor id (0..5 qkv, 6 = wo)
__global__ void cvt_weights(const float* s0, const float* s1, const float* s2,
                            const float* s3, const float* s4, const float* s5,
                            const float* s6,
                            __nv_bfloat16* __restrict__ qhi, __nv_bfloat16* __restrict__ qlo,
                            __nv_bfloat16* __restrict__ ohi, __nv_bfloat16* __restrict__ olo,
                            int n)
{
    int t = blockIdx.y;
    const float* s = (t==0)?s0:(t==1)?s1:(t==2)?s2:(t==3)?s3:(t==4)?s4:(t==5)?s5:s6;
    __nv_bfloat16* hi = (t < 6) ? qhi + (long long)t*n : ohi;
    __nv_bfloat16* lo = (t < 6) ? qlo + (long long)t*n : olo;
    int i = blockIdx.x * 256 + threadIdx.x;
    if (i < n) {
        float v = s[i];
        __nv_bfloat16 h = __float2bfloat16(v);
        hi[i] = h;
        lo[i] = __float2bfloat16(v - __bfloat162float(h));
    }
}

// ================= WMMA GEMM (128x128 tile, bf16 HMMA, fp32 accum) =================
union SmemU {
    struct { __nv_bfloat16 A[2][128][48]; __nv_bfloat16 B[2][32][136]; } ld;
    float st[64][132];
};

// ---------------- QKV GEMM: C_w[b](128 x ncols) = W_w(128x512) * X[b](512 x ncols) ----
__global__ __launch_bounds__(256)
void wmma_qkv(const __nv_bfloat16* __restrict__ whi, const __nv_bfloat16* __restrict__ wlo,
              const __nv_bfloat16* __restrict__ xhi, const __nv_bfloat16* __restrict__ xlo,
              float* __restrict__ Cq, float* __restrict__ Ck, float* __restrict__ Cv,
              int ncols, int ldb, long long bStride, long long cStride)
{
    __shared__ SmemU sm;
    int tid = threadIdx.x;
    int w = blockIdx.x;
    int b = blockIdx.z;
    int colBase = blockIdx.y * 128;

    const __nv_bfloat16* Ahi = whi + (long long)w * (2*FF*DD);
    const __nv_bfloat16* Alo = wlo + (long long)w * (2*FF*DD);
    const __nv_bfloat16* Bhi = xhi + (long long)b * bStride;
    const __nv_bfloat16* Blo = xlo + (long long)b * bStride;
    float* C = ((w == 0) ? Cq : (w == 1) ? Ck : Cv) + (long long)b * cStride;

    const __nv_bfloat16* Asel[3] = {Ahi, Ahi, Alo};
    const __nv_bfloat16* Bsel[3] = {Bhi, Blo, Bhi};

    int warp = tid >> 5;
    int wm = warp & 3;
    int wn = warp >> 2;

    wmma::fragment<wmma::accumulator, 16, 16, 16, float> acc[2][4];
    #pragma unroll
    for (int i = 0; i < 2; i++)
        #pragma unroll
        for (int j = 0; j < 4; j++)
            wmma::fill_fragment(acc[i][j], 0.f);

    auto loadChunk = [&](int c, int buf) {
        int term = c >> 4;
        int kb = (c & 15) * 32;
        const __nv_bfloat16* As = Asel[term];
        const __nv_bfloat16* Bs = Bsel[term];
        #pragma unroll
        for (int r = 0; r < 2; r++) {
            int e = tid + r*256;
            int m = e >> 2, k8 = (e & 3) * 8;
            cpa16(&sm.ld.A[buf][m][k8], &As[(long long)m*DD + kb + k8]);
        }
        #pragma unroll
        for (int r = 0; r < 2; r++) {
            int e = tid + r*256;
            int k = e >> 4, n8 = (e & 15) * 8;
            cpa16(&sm.ld.B[buf][k][n8], &Bs[(long long)(kb + k)*ldb + colBase + n8]);
        }
        CPA_COMMIT();
    };

    const int NCH = 48;
    loadChunk(0, 0);
    for (int c = 0; c < NCH; c++) {
        int cb = c & 1;
        if (c + 1 < NCH) {
            loadChunk(c + 1, (c + 1) & 1);
            asm volatile("cp.async.wait_group 1;");
        } else {
            asm volatile("cp.async.wait_group 0;");
        }
        __syncthreads();
        #pragma unroll
        for (int ks = 0; ks < 32; ks += 16) {
            wmma::fragment<wmma::matrix_a, 16, 16, 16, __nv_bfloat16, wmma::row_major> af[2];
            wmma::fragment<wmma::matrix_b, 16, 16, 16, __nv_bfloat16, wmma::row_major> bf[4];
            #pragma unroll
            for (int i = 0; i < 2; i++)
                wmma::load_matrix_sync(af[i], &sm.ld.A[cb][wm*32 + i*16][ks], 48);
            #pragma unroll
            for (int j = 0; j < 4; j++)
                wmma::load_matrix_sync(bf[j], &sm.ld.B[cb][ks][wn*64 + j*16], 136);
            #pragma unroll
            for (int i = 0; i < 2; i++)
                #pragma unroll
                for (int j = 0; j < 4; j++)
                    wmma::mma_sync(acc[i][j], af[i], bf[j], acc[i][j]);
        }
        __syncthreads();
    }

    #pragma unroll
    for (int h = 0; h < 2; h++) {
        if (wm >= h*2 && wm < h*2 + 2) {
            #pragma unroll
            for (int i = 0; i < 2; i++)
                #pragma unroll
                for (int j = 0; j < 4; j++)
                    wmma::store_matrix_sync(&sm.st[(wm - h*2)*32 + i*16][wn*64 + j*16],
                                            acc[i][j], 132, wmma::mem_row_major);
        }
        __syncthreads();
        for (int e = tid; e < 64*128; e += 256) {
            int m = e >> 7, col = e & 127;
            int gc = colBase + col;
            if (gc < ncols) C[(long long)(h*64 + m)*ncols + gc] = sm.st[m][col];
        }
        __syncthreads();
    }
}

// ---- output projection: x[b, rowBase+m, DM+col] += relu(wo(512x128) @ pv[b](128x2688)) ----
__global__ __launch_bounds__(256)
void wmma_wo(const __nv_bfloat16* __restrict__ whi, const __nv_bfloat16* __restrict__ wlo,
             const __nv_bfloat16* __restrict__ phi, const __nv_bfloat16* __restrict__ plo,
             float* __restrict__ x)
{
    __shared__ SmemU sm;
    int tid = threadIdx.x;
    int rowBase = blockIdx.x * 128;
    int b = blockIdx.z;
    int colBase = blockIdx.y * 128;

    const __nv_bfloat16* Bhi = phi + (long long)b * (FF*OM);
    const __nv_bfloat16* Blo = plo + (long long)b * (FF*OM);

    const __nv_bfloat16* Asel[3] = {whi, whi, wlo};
    const __nv_bfloat16* Bsel[3] = {Bhi, Blo, Bhi};

    int warp = tid >> 5;
    int wm = warp & 3;
    int wn = warp >> 2;

    wmma::fragment<wmma::accumulator, 16, 16, 16, float> acc[2][4];
    #pragma unroll
    for (int i = 0; i < 2; i++)
        #pragma unroll
        for (int j = 0; j < 4; j++)
            wmma::fill_fragment(acc[i][j], 0.f);

    auto loadChunk = [&](int c, int buf) {
        int term = c >> 2;
        int kb = (c & 3) * 32;
        const __nv_bfloat16* As = Asel[term];
        const __nv_bfloat16* Bs = Bsel[term];
        #pragma unroll
        for (int r = 0; r < 2; r++) {
            int e = tid + r*256;
            int m = e >> 2, k8 = (e & 3) * 8;
            cpa16(&sm.ld.A[buf][m][k8], &As[(long long)(rowBase + m)*FF + kb + k8]);
        }
        #pragma unroll
        for (int r = 0; r < 2; r++) {
            int e = tid + r*256;
            int k = e >> 4, n8 = (e & 15) * 8;
            cpa16(&sm.ld.B[buf][k][n8], &Bs[(long long)(kb + k)*OM + colBase + n8]);
        }
        CPA_COMMIT();
    };

    const int NCH = 12;
    loadChunk(0, 0);
    for (int c = 0; c < NCH; c++) {
        int cb = c & 1;
        if (c + 1 < NCH) {
            loadChunk(c + 1, (c + 1) & 1);
            asm volatile("cp.async.wait_group 1;");
        } else {
            asm volatile("cp.async.wait_group 0;");
        }
        __syncthreads();
        #pragma unroll
        for (int ks = 0; ks < 32; ks += 16) {
            wmma::fragment<wmma::matrix_a, 16, 16, 16, __nv_bfloat16, wmma::row_major> af[2];
            wmma::fragment<wmma::matrix_b, 16, 16, 16, __nv_bfloat16, wmma::row_major> bf[4];
            #pragma unroll
            for (int i = 0; i < 2; i++)
                wmma::load_matrix_sync(af[i], &sm.ld.A[cb][wm*32 + i*16][ks], 48);
            #pragma unroll
            for (int j = 0; j < 4; j++)
                wmma::load_matrix_sync(bf[j], &sm.ld.B[cb][ks][wn*64 + j*16], 136);
            #pragma unroll
            for (int i = 0; i < 2; i++)
                #pragma unroll
                for (int j = 0; j < 4; j++)
                    wmma::mma_sync(acc[i][j], af[i], bf[j], acc[i][j]);
        }
        __syncthreads();
    }

    #pragma unroll
    for (int h = 0; h < 2; h++) {
        if (wm >= h*2 && wm < h*2 + 2) {
            #pragma unroll
            for (int i = 0; i < 2; i++)
                #pragma unroll
                for (int j = 0; j < 4; j++)
                    wmma::store_matrix_sync(&sm.st[(wm - h*2)*32 + i*16][wn*64 + j*16],
                                            acc[i][j], 132, wmma::mem_row_major);
        }
        __syncthreads();
        for (int e = tid; e < 64*128; e += 256) {
            int m = e >> 7, col = e & 127;
            long long xi = ((long long)(b*DD + rowBase + h*64 + m))*SPAT + DM + colBase + col;
            x[xi] += fmaxf(sm.st[m][col], 0.f);
        }
        __syncthreads();
    }
}

// ---------------- blocked demo attention + dv_att, one block per (b, n, ti) ----------------
// All 84 queries i in time-tile ti share the same causal extent nvalid=(ti+1)*84.
// S stored transposed [j][i] so softmax-per-i and PV are coalesced.
// dynamic smem layout (floats):
//   Ks[32][84], Vs[32][336], Qt[32][64], S[336][85], invs[84]
#define DSM_KS   0
#define DSM_VS   (32*84)
#define DSM_QT   (DSM_VS + 32*336)
#define DSM_S    (DSM_QT + 32*64)
#define DSM_INV  (DSM_S + 336*85)
#define DSM_FLOATS (DSM_INV + 84)
#define DSM_BYTES  (DSM_FLOATS*4)

__global__ __launch_bounds__(256)
void demo_attn_kernel(const float* __restrict__ dk,
                      const float* __restrict__ dq,
                      const float* __restrict__ dv,
                      float* __restrict__ dvatt)
{
    extern __shared__ float dsm[];
    float* Ks   = dsm + DSM_KS;    // K at query positions [c][i]
    float* Vs   = dsm + DSM_VS;    // V at key positions   [c][j] (rows 336 wide)
    float* Qt   = dsm + DSM_QT;    // Q key chunk          [c][jj] (64 wide)
    float* S    = dsm + DSM_S;     // logits/probs [j][i], rows 85 wide
    float* invs = dsm + DSM_INV;

    int ti = blockIdx.x;           // 0..3
    int n  = blockIdx.y;
    int b  = blockIdx.z;
    const long long base = ((long long)b*FF + n*CH) * DM;
    const int nvalid = (ti + 1) * HWW;   // uniform causal bound for this tile

    int tid = threadIdx.x;

    // load K (at queries) and V (all valid keys)
    for (int l = tid; l < CH*HWW; l += 256) {
        int c = l / HWW, i = l % HWW;
        Ks[c*HWW + i] = dk[base + (long long)c*DM + ti*HWW + i];
    }
    for (int l = tid; l < CH*nvalid; l += 256) {
        int c = l / nvalid, j = l % nvalid;
        Vs[c*DM + j] = dv[base + (long long)c*DM + j];
    }
    __syncthreads();

    // phase 1: logits S[j][i] = sum_c dk[c,i]*dq[c,j] * INV_TEMP, chunks of 64 keys
    int tx = tid % 16, ty = tid / 16;
    int nch = (nvalid + 63) / 64;
    for (int chk = 0; chk < nch; chk++) {
        int j0 = chk * 64;
        for (int l = tid; l < CH*64; l += 256) {
            int c = l >> 6, jj = l & 63;
            int j = j0 + jj;
            Qt[c*64 + jj] = (j < nvalid) ? dq[base + (long long)c*DM + j] : 0.f;
        }
        __syncthreads();
        float sa[4][6] = {};
        #pragma unroll
        for (int c = 0; c < CH; c++) {
            float a[4], bq[6];
            #pragma unroll
            for (int pp = 0; pp < 4; pp++) a[pp] = Qt[c*64 + ty*4 + pp];
            #pragma unroll
            for (int ii = 0; ii < 6; ii++) {
                int i = tx*6 + ii;
                bq[ii] = (i < HWW) ? Ks[c*HWW + i] : 0.f;
            }
            #pragma unroll
            for (int pp = 0; pp < 4; pp++)
                #pragma unroll
                for (int ii = 0; ii < 6; ii++)
                    sa[pp][ii] += a[pp] * bq[ii];
        }
        #pragma unroll
        for (int pp = 0; pp < 4; pp++) {
            int j = j0 + ty*4 + pp;
            #pragma unroll
            for (int ii = 0; ii < 6; ii++) {
                int i = tx*6 + ii;
                if (i < HWW && j < nvalid) S[j*85 + i] = sa[pp][ii] * INV_TEMP;
            }
        }
        __syncthreads();
    }

    // phase 2: softmax over j per query i (2 threads per i, shfl pair reduce)
    {
        int i = tid >> 1, h = tid & 1;
        float mx = -1e30f, sum = 0.f;
        if (i < HWW) {
            for (int j = h; j < nvalid; j += 2) mx = fmaxf(mx, S[j*85 + i]);
        }
        mx = fmaxf(mx, __shfl_xor_sync(0xffffffffu, mx, 1));
        if (i < HWW) {
            for (int j = h; j < nvalid; j += 2) {
                float e = __expf(S[j*85 + i] - mx);
                S[j*85 + i] = e;
                sum += e;
            }
        }
        sum += __shfl_xor_sync(0xffffffffu, sum, 1);
        if (i < HWW && h == 0) invs[i] = 1.f / sum;
    }
    __syncthreads();

    // phase 3: dvatt[c, ti*84+i] = inv[i] * sum_j Vs[c][j] * S[j][i]
    int warp = tid >> 5, lane = tid & 31;
    int c0 = warp * 4;
    float acc[4][3] = {};
    for (int j = 0; j < nvalid; j += 4) {
        float4 v[4];
        #pragma unroll
        for (int cc = 0; cc < 4; cc++)
            v[cc] = *(const float4*)&Vs[(c0 + cc)*DM + j];
        #pragma unroll
        for (int q = 0; q < 4; q++) {
            const float* Sr = &S[(j + q)*85];
            float s0 = Sr[lane];
            float s1 = Sr[lane + 32];
            float s2 = (lane < HWW - 64) ? Sr[lane + 64] : 0.f;
            #pragma unroll
            for (int cc = 0; cc < 4; cc++) {
                float vq = (q == 0) ? v[cc].x : (q == 1) ? v[cc].y
                         : (q == 2) ? v[cc].z : v[cc].w;
                acc[cc][0] += vq * s0;
                acc[cc][1] += vq * s1;
                acc[cc][2] += vq * s2;
            }
        }
    }
    #pragma unroll
    for (int cc = 0; cc < 4; cc++) {
        long long o = base + (long long)(c0 + cc)*DM + ti*HWW;
        #pragma unroll
        for (int r = 0; r < 3; r++) {
            int i = lane + r*32;
            if (i < HWW) dvatt[o + i] = acc[cc][r] * invs[i];
        }
    }
}

// ---------------- fused obs attention per (b,t,n) ----------------
// Writes pv directly as bf16 hi/lo (feeds wmma_wo).
#define PCH 64
__global__ __launch_bounds__(256)
void obs_attn_kernel(const float* __restrict__ dk,
                     const float* __restrict__ dvatt,
                     const float* __restrict__ ok,
                     const float* __restrict__ ov,
                     const float* __restrict__ oq,
                     __nv_bfloat16* __restrict__ pvhi,
                     __nv_bfloat16* __restrict__ pvlo)
{
    int n = blockIdx.x, t = blockIdx.y, b = blockIdx.z;
    const long long obase = ((long long)b*FF + n*CH) * OM + (long long)t*HWW;
    const long long dbase = ((long long)b*FF + n*CH) * DM;

    __shared__ float qs[CH][HWW];
    __shared__ float ks[CH][PCH];
    __shared__ float vs[CH][PCH];
    __shared__ float S[PCH][HWW+1];

    int tid = threadIdx.x;
    int tx = tid % 16, ty = tid / 16;
    int warp = tid >> 5, lane = tid & 31;
    int c0 = warp * 4;

    for (int l = tid; l < CH*HWW; l += 256) {
        int c = l / HWW, j = l % HWW;
        qs[c][j] = oq[obase + (long long)c*OM + j];
    }

    float acc[4][3] = {};

    for (int p0 = 0; p0 < CATP; p0 += PCH) {
        for (int l = tid; l < CH*PCH; l += 256) {
            int c = l / PCH, pl = l % PCH;
            int p = p0 + pl;
            float kk = 0.f, vv = 0.f;
            if (p < DM) {
                kk = dk   [dbase + (long long)c*DM + p];
                vv = dvatt[dbase + (long long)c*DM + p];
            } else if (p < CATP) {
                kk = ok[obase + (long long)c*OM + (p - DM)];
                vv = ov[obase + (long long)c*OM + (p - DM)];
            }
            ks[c][pl] = kk; vs[c][pl] = vv;
        }
        __syncthreads();

        {
            float sa[4][6] = {};
            #pragma unroll
            for (int k = 0; k < CH; k++) {
                float a[4], bq[6];
                #pragma unroll
                for (int pp = 0; pp < 4; pp++) a[pp] = ks[k][ty*4 + pp];
                #pragma unroll
                for (int jj = 0; jj < 6; jj++) {
                    int j = tx*6 + jj;
                    bq[jj] = (j < HWW) ? qs[k][j] : 0.f;
                }
                #pragma unroll
                for (int pp = 0; pp < 4; pp++)
                    #pragma unroll
                    for (int jj = 0; jj < 6; jj++)
                        sa[pp][jj] += a[pp] * bq[jj];
            }
            #pragma unroll
            for (int pp = 0; pp < 4; pp++)
                #pragma unroll
                for (int jj = 0; jj < 6; jj++) {
                    int j = tx*6 + jj;
                    if (j < HWW) S[ty*4 + pp][j] = sa[pp][jj] * INV_TEMP;
                }
        }
        __syncthreads();

        {
            int row = tid >> 2;
            int l4  = tid & 3;
            float mx = -1e30f;
            for (int j = l4; j < HWW; j += 4) mx = fmaxf(mx, S[row][j]);
            mx = fmaxf(mx, __shfl_xor_sync(0xffffffffu, mx, 1));
            mx = fmaxf(mx, __shfl_xor_sync(0xffffffffu, mx, 2));
            float sum = 0.f;
            for (int j = l4; j < HWW; j += 4) {
                float e = __expf(S[row][j] - mx);
                S[row][j] = e;
                sum += e;
            }
            sum += __shfl_xor_sync(0xffffffffu, sum, 1);
            sum += __shfl_xor_sync(0xffffffffu, sum, 2);
            float iv = 1.f / sum;
            bool valid = (p0 + row) < CATP;
            for (int j = l4; j < HWW; j += 4)
                S[row][j] = valid ? S[row][j] * iv : 0.f;
        }
        __syncthreads();

        #pragma unroll 2
        for (int pl = 0; pl < PCH; pl += 4) {
            float4 v[4];
            #pragma unroll
            for (int cc = 0; cc < 4; cc++)
                v[cc] = *(const float4*)&vs[c0 + cc][pl];
            #pragma unroll
            for (int q = 0; q < 4; q++) {
                float s0 = S[pl + q][lane];
                float s1 = S[pl + q][lane + 32];
                float s2 = (lane < HWW - 64) ? S[pl + q][lane + 64] : 0.f;
                #pragma unroll
                for (int cc = 0; cc < 4; cc++) {
                    float vq = (q == 0) ? v[cc].x : (q == 1) ? v[cc].y
                             : (q == 2) ? v[cc].z : v[cc].w;
                    acc[cc][0] += vq * s0;
                    acc[cc][1] += vq * s1;
                    acc[cc][2] += vq * s2;
                }
            }
        }
        __syncthreads();
    }

    #pragma unroll
    for (int cc = 0; cc < 4; cc++) {
        long long o = obase + (long long)(c0 + cc)*OM;
        #pragma unroll
        for (int r = 0; r < 3; r++) {
            int j = lane + r*32;
            if (j < HWW) {
                float vv = acc[cc][r];
                __nv_bfloat16 h = __float2bfloat16(vv);
                pvhi[o + j] = h;
                pvlo[o + j] = __float2bfloat16(vv - __bfloat162float(h));
            }
        }
    }
}

// ---------------- batchnorm + optional fused bf16 hi/lo split of the output ----------------
__global__ void bn_kernel(const float* __restrict__ x, float* __restrict__ out,
                          const float* __restrict__ gamma, const float* __restrict__ beta,
                          __nv_bfloat16* __restrict__ hi, __nv_bfloat16* __restrict__ lo)
{
    int ch = blockIdx.x;
    int tid = threadIdx.x;
    const long long chOff = (long long)ch * SPAT;

    double s = 0.0, s2 = 0.0;
    for (int b = 0; b < BB; b++) {
        const float* p = x + (long long)b*DD*SPAT + chOff;
        for (int idx = tid; idx < SPAT; idx += 256) {
            float v = p[idx];
            s  += v;
            s2 += (double)v * v;
        }
    }
    __shared__ double rs[256], rs2[256];
    rs[tid] = s; rs2[tid] = s2; __syncthreads();
    for (int o = 128; o > 0; o >>= 1) {
        if (tid < o) { rs[tid] += rs[tid+o]; rs2[tid] += rs2[tid+o]; }
        __syncthreads();
    }
    const double cnt = (double)BB * SPAT;
    double mean = rs[0] / cnt;
    double var  = rs2[0] / cnt - mean*mean;
    float scale = (float)((double)gamma[ch] * rsqrt(var + 1e-5));
    float mn = (float)mean;
    float bt = beta[ch];
    for (int b = 0; b < BB; b++) {
        const long long off = (long long)b*DD*SPAT + chOff;
        const float* p = x + off;
        float*       q = out + off;
        for (int idx = tid; idx < SPAT; idx += 256) {
            float y = scale * (p[idx] - mn) + bt;
            q[idx] = y;
            if (hi) {
                __nv_bfloat16 h = __float2bfloat16(y);
                hi[off + idx] = h;
                lo[off + idx] = __float2bfloat16(y - __bfloat162float(h));
            }
        }
    }
}

// ---------------- host driver ----------------
extern "C" void kernel_launch(void* const* d_in, const int* in_sizes, int n_in,
                              void* d_out, int out_size)
{
    const float* inputs  = (const float*)d_in[0];
    const float* demo_wq = (const float*)d_in[1];
    const float* demo_wk = (const float*)d_in[2];
    const float* demo_wv = (const float*)d_in[3];
    // demo_wo (d_in[4]) unused by the reference
    const float* obs_wq  = (const float*)d_in[5];
    const float* obs_wk  = (const float*)d_in[6];
    const float* obs_wv  = (const float*)d_in[7];
    const float* obs_wo  = (const float*)d_in[8];
    const float* bn_g    = (const float*)d_in[9];
    const float* bn_b    = (const float*)d_in[10];
    float* out = (float*)d_out;

    float *xp, *dqp, *dkp, *dvp, *dvattp, *oqp, *okp, *ovp;
    __nv_bfloat16 *xhip, *xlop, *pvhip, *pvlop, *wqhip, *wqlop, *wohip, *wolop;
    cudaGetSymbolAddress((void**)&xp,     g_x);
    cudaGetSymbolAddress((void**)&dqp,    g_dq);
    cudaGetSymbolAddress((void**)&dkp,    g_dk);
    cudaGetSymbolAddress((void**)&dvp,    g_dv);
    cudaGetSymbolAddress((void**)&dvattp, g_dvatt);
    cudaGetSymbolAddress((void**)&oqp,    g_oq);
    cudaGetSymbolAddress((void**)&okp,    g_ok);
    cudaGetSymbolAddress((void**)&ovp,    g_ov);
    cudaGetSymbolAddress((void**)&xhip,   g_xhi);
    cudaGetSymbolAddress((void**)&xlop,   g_xlo);
    cudaGetSymbolAddress((void**)&pvhip,  g_pvhi);
    cudaGetSymbolAddress((void**)&pvlop,  g_pvlo);
    cudaGetSymbolAddress((void**)&wqhip,  g_wqhi);
    cudaGetSymbolAddress((void**)&wqlop,  g_wqlo);
    cudaGetSymbolAddress((void**)&wohip,  g_wohi);
    cudaGetSymbolAddress((void**)&wolop,  g_wolo);

    // demo_attn needs ~177KB dynamic smem (config call, not an allocation)
    cudaFuncSetAttribute(demo_attn_kernel,
                         cudaFuncAttributeMaxDynamicSharedMemorySize, DSM_BYTES);

    cudaMemcpyAsync(xp, inputs, (size_t)BB*DD*SPAT*sizeof(float),
                    cudaMemcpyDeviceToDevice, 0);

    // convert all 7 weight tensors in one launch
    const int WT = 2*FF*DD;
    cvt_weights<<<dim3(WT/256, 7), 256>>>(demo_wq, demo_wk, demo_wv,
                                          obs_wq, obs_wk, obs_wv, obs_wo,
                                          wqhip, wqlop, wohip, wolop, WT);

    const long long XEL = (long long)BB*DD*SPAT;
    const long long XB  = (long long)DD*SPAT;
    const long long QD  = (long long)FF*DM;
    const long long QO  = (long long)FF*OM;

    // initial bf16 split of x (layer 1's split is fused into bn_kernel)
    cvt_pair<<<(unsigned)((XEL + 255)/256), 256>>>(xp, xhip, xlop, (int)XEL);

    for (int i = 0; i < 2; i++) {
        const long long lw = (long long)i*FF*DD;

        // demo QKV (tensor cores)
        wmma_qkv<<<dim3(3, (DM + 127)/128, BB), 256>>>(
            wqhip + lw, wqlop + lw, xhip, xlop,
            dqp, dkp, dvp, DM, SPAT, XB, QD);

        // blocked demo attention + dv_att
        demo_attn_kernel<<<dim3(DEMO_TT, NH, BB), 256, DSM_BYTES>>>(dkp, dqp, dvp, dvattp);

        // obs QKV
        wmma_qkv<<<dim3(3, OM/128, BB), 256>>>(
            wqhip + 3LL*WT + lw, wqlop + 3LL*WT + lw, xhip + DM, xlop + DM,
            oqp, okp, ovp, OM, SPAT, XB, QO);

        // obs attention -> pv bf16 hi/lo directly
        obs_attn_kernel<<<dim3(NH, OBS_TT, BB), 256>>>(dkp, dvattp, okp, ovp, oqp,
                                                       pvhip, pvlop);

        // output projection + residual + relu into x
        wmma_wo<<<dim3(DD/128, OM/128, BB), 256>>>(
            wohip + lw, wolop + lw, pvhip, pvlop, xp);

        // batchnorm; layer 0 also emits next layer's bf16 split
        bn_kernel<<<DD, 256>>>(xp, (i == 1) ? out : xp, bn_g + i*DD, bn_b + i*DD,
                               (i == 0) ? xhip : (__nv_bfloat16*)nullptr,
                               (i == 0) ? xlop : (__nv_bfloat16*)nullptr);
    }
}

// round 17
// speedup vs baseline: 1.2793x; 1.0113x over previous
#include <cuda_runtime.h>
#include <cuda_bf16.h>
#include <mma.h>
#include <cstdint>

using namespace nvcuda;

// ---------------- problem constants ----------------
#define BB 8
#define DD 512
#define T_TOT 36
#define DEMO_TT 4
#define OBS_TT 32
#define HWW 84
#define FF 128
#define NH 4
#define CH 32               // channels per head
#define DM (DEMO_TT*HWW)    // 336 demo positions
#define OM (OBS_TT*HWW)     // 2688 obs positions
#define CATP (DM+HWW)       // 420 concat positions
#define SPAT (T_TOT*HWW)    // 3024

static constexpr float INV_TEMP = 0.044194173824159216f; // 1/sqrt(512)

// ---------------- device scratch (no cudaMalloc allowed) ----------------
__device__ float g_x    [BB*DD*SPAT];    // running activation (B,512,36,84)
__device__ float g_dq   [BB*FF*DM];
__device__ float g_dk   [BB*FF*DM];
__device__ float g_dv   [BB*FF*DM];
__device__ float g_dvatt[BB*FF*DM];
__device__ float g_oq   [BB*FF*OM];
__device__ float g_ok   [BB*FF*OM];
__device__ float g_ov   [BB*FF*OM];

// bf16 hi/lo split operands for tensor-core GEMMs
__device__ __nv_bfloat16 g_xhi [BB*DD*SPAT];
__device__ __nv_bfloat16 g_xlo [BB*DD*SPAT];
__device__ __nv_bfloat16 g_pvhi[BB*FF*OM];
__device__ __nv_bfloat16 g_pvlo[BB*FF*OM];
// packed qkv weights: [tensor 0..5][layer 0..1][FF*DD], tensors: dq,dk,dv,oq,ok,ov
__device__ __nv_bfloat16 g_wqhi[6*2*FF*DD];
__device__ __nv_bfloat16 g_wqlo[6*2*FF*DD];
__device__ __nv_bfloat16 g_wohi[2*DD*FF];
__device__ __nv_bfloat16 g_wolo[2*DD*FF];

// ---------------- cp.async helpers (sm_80+ baseline features) ----------------
__device__ __forceinline__ void cpa16(void* dst_smem, const void* src) {
    uint32_t d = (uint32_t)__cvta_generic_to_shared(dst_smem);
    asm volatile("cp.async.cg.shared.global [%0], [%1], 16;" :: "r"(d), "l"(src));
}
#define CPA_COMMIT() asm volatile("cp.async.commit_group;")

// ---------------- fp32 -> bf16 hi/lo split ----------------
__global__ void cvt_pair(const float* __restrict__ s, __nv_bfloat16* __restrict__ hi,
                         __nv_bfloat16* __restrict__ lo, int n)
{
    int i = blockIdx.x * 256 + threadIdx.x;
    if (i < n) {
        float v = s[i];
        __nv_bfloat16 h = __float2bfloat16(v);
        hi[i] = h;
        lo[i] = __float2bfloat16(v - __bfloat162float(h));
    }
}

// all 7 weight tensors in one launch: blockIdx.y = tensor id (0..5 qkv, 6 = wo)
__global__ void cvt_weights(const float* s0, const float* s1, const float* s2,
                            const float* s3, const float* s4, const float* s5,
                            const float* s6,
                            __nv_bfloat16* __restrict__ qhi, __nv_bfloat16* __restrict__ qlo,
                            __nv_bfloat16* __restrict__ ohi, __nv_bfloat16* __restrict__ olo,
                            int n)
{
    int t = blockIdx.y;
    const float* s = (t==0)?s0:(t==1)?s1:(t==2)?s2:(t==3)?s3:(t==4)?s4:(t==5)?s5:s6;
    __nv_bfloat16* hi = (t < 6) ? qhi + (long long)t*n : ohi;
    __nv_bfloat16* lo = (t < 6) ? qlo + (long long)t*n : olo;
    int i = blockIdx.x * 256 + threadIdx.x;
    if (i < n) {
        float v = s[i];
        __nv_bfloat16 h = __float2bfloat16(v);
        hi[i] = h;
        lo[i] = __float2bfloat16(v - __bfloat162float(h));
    }
}

// ================= WMMA GEMM (128x128 tile, bf16 HMMA, fp32 accum) =================
union SmemU {
    struct { __nv_bfloat16 A[2][128][48]; __nv_bfloat16 B[2][32][136]; } ld;
    float st[64][132];
};

// ---------------- QKV GEMM: C_w[b](128 x ncols) = W_w(128x512) * X[b](512 x ncols) ----
__global__ __launch_bounds__(256)
void wmma_qkv(const __nv_bfloat16* __restrict__ whi, const __nv_bfloat16* __restrict__ wlo,
              const __nv_bfloat16* __restrict__ xhi, const __nv_bfloat16* __restrict__ xlo,
              float* __restrict__ Cq, float* __restrict__ Ck, float* __restrict__ Cv,
              int ncols, int ldb, long long bStride, long long cStride)
{
    __shared__ SmemU sm;
    int tid = threadIdx.x;
    int w = blockIdx.x;
    int b = blockIdx.z;
    int colBase = blockIdx.y * 128;

    const __nv_bfloat16* Ahi = whi + (long long)w * (2*FF*DD);
    const __nv_bfloat16* Alo = wlo + (long long)w * (2*FF*DD);
    const __nv_bfloat16* Bhi = xhi + (long long)b * bStride;
    const __nv_bfloat16* Blo = xlo + (long long)b * bStride;
    float* C = ((w == 0) ? Cq : (w == 1) ? Ck : Cv) + (long long)b * cStride;

    const __nv_bfloat16* Asel[3] = {Ahi, Ahi, Alo};
    const __nv_bfloat16* Bsel[3] = {Bhi, Blo, Bhi};

    int warp = tid >> 5;
    int wm = warp & 3;
    int wn = warp >> 2;

    wmma::fragment<wmma::accumulator, 16, 16, 16, float> acc[2][4];
    #pragma unroll
    for (int i = 0; i < 2; i++)
        #pragma unroll
        for (int j = 0; j < 4; j++)
            wmma::fill_fragment(acc[i][j], 0.f);

    auto loadChunk = [&](int c, int buf) {
        int term = c >> 4;
        int kb = (c & 15) * 32;
        const __nv_bfloat16* As = Asel[term];
        const __nv_bfloat16* Bs = Bsel[term];
        #pragma unroll
        for (int r = 0; r < 2; r++) {
            int e = tid + r*256;
            int m = e >> 2, k8 = (e & 3) * 8;
            cpa16(&sm.ld.A[buf][m][k8], &As[(long long)m*DD + kb + k8]);
        }
        #pragma unroll
        for (int r = 0; r < 2; r++) {
            int e = tid + r*256;
            int k = e >> 4, n8 = (e & 15) * 8;
            cpa16(&sm.ld.B[buf][k][n8], &Bs[(long long)(kb + k)*ldb + colBase + n8]);
        }
        CPA_COMMIT();
    };

    const int NCH = 48;
    loadChunk(0, 0);
    for (int c = 0; c < NCH; c++) {
        int cb = c & 1;
        if (c + 1 < NCH) {
            loadChunk(c + 1, (c + 1) & 1);
            asm volatile("cp.async.wait_group 1;");
        } else {
            asm volatile("cp.async.wait_group 0;");
        }
        __syncthreads();
        #pragma unroll
        for (int ks = 0; ks < 32; ks += 16) {
            wmma::fragment<wmma::matrix_a, 16, 16, 16, __nv_bfloat16, wmma::row_major> af[2];
            wmma::fragment<wmma::matrix_b, 16, 16, 16, __nv_bfloat16, wmma::row_major> bf[4];
            #pragma unroll
            for (int i = 0; i < 2; i++)
                wmma::load_matrix_sync(af[i], &sm.ld.A[cb][wm*32 + i*16][ks], 48);
            #pragma unroll
            for (int j = 0; j < 4; j++)
                wmma::load_matrix_sync(bf[j], &sm.ld.B[cb][ks][wn*64 + j*16], 136);
            #pragma unroll
            for (int i = 0; i < 2; i++)
                #pragma unroll
                for (int j = 0; j < 4; j++)
                    wmma::mma_sync(acc[i][j], af[i], bf[j], acc[i][j]);
        }
        __syncthreads();
    }

    #pragma unroll
    for (int h = 0; h < 2; h++) {
        if (wm >= h*2 && wm < h*2 + 2) {
            #pragma unroll
            for (int i = 0; i < 2; i++)
                #pragma unroll
                for (int j = 0; j < 4; j++)
                    wmma::store_matrix_sync(&sm.st[(wm - h*2)*32 + i*16][wn*64 + j*16],
                                            acc[i][j], 132, wmma::mem_row_major);
        }
        __syncthreads();
        for (int e = tid; e < 64*128; e += 256) {
            int m = e >> 7, col = e & 127;
            int gc = colBase + col;
            if (gc < ncols) C[(long long)(h*64 + m)*ncols + gc] = sm.st[m][col];
        }
        __syncthreads();
    }
}

// ---- output projection: x[b, rowBase+m, DM+col] += relu(wo(512x128) @ pv[b](128x2688)) ----
__global__ __launch_bounds__(256)
void wmma_wo(const __nv_bfloat16* __restrict__ whi, const __nv_bfloat16* __restrict__ wlo,
             const __nv_bfloat16* __restrict__ phi, const __nv_bfloat16* __restrict__ plo,
             float* __restrict__ x)
{
    __shared__ SmemU sm;
    int tid = threadIdx.x;
    int rowBase = blockIdx.x * 128;
    int b = blockIdx.z;
    int colBase = blockIdx.y * 128;

    const __nv_bfloat16* Bhi = phi + (long long)b * (FF*OM);
    const __nv_bfloat16* Blo = plo + (long long)b * (FF*OM);

    const __nv_bfloat16* Asel[3] = {whi, whi, wlo};
    const __nv_bfloat16* Bsel[3] = {Bhi, Blo, Bhi};

    int warp = tid >> 5;
    int wm = warp & 3;
    int wn = warp >> 2;

    wmma::fragment<wmma::accumulator, 16, 16, 16, float> acc[2][4];
    #pragma unroll
    for (int i = 0; i < 2; i++)
        #pragma unroll
        for (int j = 0; j < 4; j++)
            wmma::fill_fragment(acc[i][j], 0.f);

    auto loadChunk = [&](int c, int buf) {
        int term = c >> 2;
        int kb = (c & 3) * 32;
        const __nv_bfloat16* As = Asel[term];
        const __nv_bfloat16* Bs = Bsel[term];
        #pragma unroll
        for (int r = 0; r < 2; r++) {
            int e = tid + r*256;
            int m = e >> 2, k8 = (e & 3) * 8;
            cpa16(&sm.ld.A[buf][m][k8], &As[(long long)(rowBase + m)*FF + kb + k8]);
        }
        #pragma unroll
        for (int r = 0; r < 2; r++) {
            int e = tid + r*256;
            int k = e >> 4, n8 = (e & 15) * 8;
            cpa16(&sm.ld.B[buf][k][n8], &Bs[(long long)(kb + k)*OM + colBase + n8]);
        }
        CPA_COMMIT();
    };

    const int NCH = 12;
    loadChunk(0, 0);
    for (int c = 0; c < NCH; c++) {
        int cb = c & 1;
        if (c + 1 < NCH) {
            loadChunk(c + 1, (c + 1) & 1);
            asm volatile("cp.async.wait_group 1;");
        } else {
            asm volatile("cp.async.wait_group 0;");
        }
        __syncthreads();
        #pragma unroll
        for (int ks = 0; ks < 32; ks += 16) {
            wmma::fragment<wmma::matrix_a, 16, 16, 16, __nv_bfloat16, wmma::row_major> af[2];
            wmma::fragment<wmma::matrix_b, 16, 16, 16, __nv_bfloat16, wmma::row_major> bf[4];
            #pragma unroll
            for (int i = 0; i < 2; i++)
                wmma::load_matrix_sync(af[i], &sm.ld.A[cb][wm*32 + i*16][ks], 48);
            #pragma unroll
            for (int j = 0; j < 4; j++)
                wmma::load_matrix_sync(bf[j], &sm.ld.B[cb][ks][wn*64 + j*16], 136);
            #pragma unroll
            for (int i = 0; i < 2; i++)
                #pragma unroll
                for (int j = 0; j < 4; j++)
                    wmma::mma_sync(acc[i][j], af[i], bf[j], acc[i][j]);
        }
        __syncthreads();
    }

    #pragma unroll
    for (int h = 0; h < 2; h++) {
        if (wm >= h*2 && wm < h*2 + 2) {
            #pragma unroll
            for (int i = 0; i < 2; i++)
                #pragma unroll
                for (int j = 0; j < 4; j++)
                    wmma::store_matrix_sync(&sm.st[(wm - h*2)*32 + i*16][wn*64 + j*16],
                                            acc[i][j], 132, wmma::mem_row_major);
        }
        __syncthreads();
        for (int e = tid; e < 64*128; e += 256) {
            int m = e >> 7, col = e & 127;
            long long xi = ((long long)(b*DD + rowBase + h*64 + m))*SPAT + DM + colBase + col;
            x[xi] += fmaxf(sm.st[m][col], 0.f);
        }
        __syncthreads();
    }
}

// ---------------- blocked demo attention + dv_att, one block per (b, n, ti) ----------------
// dynamic smem layout (floats):
//   Ks[32][84], Vs[32][336], Qt[32][64], S[336][85], invs[84]
#define DSM_KS   0
#define DSM_VS   (32*84)
#define DSM_QT   (DSM_VS + 32*336)
#define DSM_S    (DSM_QT + 32*64)
#define DSM_INV  (DSM_S + 336*85)
#define DSM_FLOATS (DSM_INV + 84)
#define DSM_BYTES  (DSM_FLOATS*4)

__global__ __launch_bounds__(256)
void demo_attn_kernel(const float* __restrict__ dk,
                      const float* __restrict__ dq,
                      const float* __restrict__ dv,
                      float* __restrict__ dvatt)
{
    extern __shared__ float dsm[];
    float* Ks   = dsm + DSM_KS;
    float* Vs   = dsm + DSM_VS;
    float* Qt   = dsm + DSM_QT;
    float* S    = dsm + DSM_S;
    float* invs = dsm + DSM_INV;

    int ti = blockIdx.x;
    int n  = blockIdx.y;
    int b  = blockIdx.z;
    const long long base = ((long long)b*FF + n*CH) * DM;
    const int nvalid = (ti + 1) * HWW;

    int tid = threadIdx.x;

    for (int l = tid; l < CH*HWW; l += 256) {
        int c = l / HWW, i = l % HWW;
        Ks[c*HWW + i] = dk[base + (long long)c*DM + ti*HWW + i];
    }
    for (int l = tid; l < CH*nvalid; l += 256) {
        int c = l / nvalid, j = l % nvalid;
        Vs[c*DM + j] = dv[base + (long long)c*DM + j];
    }
    __syncthreads();

    // phase 1: logits S[j][i]; vectorized smem operand loads
    int tx = tid % 16, ty = tid / 16;
    int nch = (nvalid + 63) / 64;
    for (int chk = 0; chk < nch; chk++) {
        int j0 = chk * 64;
        for (int l = tid; l < CH*64; l += 256) {
            int c = l >> 6, jj = l & 63;
            int j = j0 + jj;
            Qt[c*64 + jj] = (j < nvalid) ? dq[base + (long long)c*DM + j] : 0.f;
        }
        __syncthreads();
        float sa[4][6] = {};
        #pragma unroll
        for (int c = 0; c < CH; c++) {
            // Qt row 16B-aligned: one LDS.128
            float4 a4 = *(const float4*)&Qt[c*64 + ty*4];
            float a[4] = {a4.x, a4.y, a4.z, a4.w};
            // Ks row 8B-aligned at tx*6: three LDS.64 (over-read past i=83 lands
            // in Vs — in-bounds smem, discarded at store)
            float2 b01 = *(const float2*)&Ks[c*HWW + tx*6];
            float2 b23 = *(const float2*)&Ks[c*HWW + tx*6 + 2];
            float2 b45 = *(const float2*)&Ks[c*HWW + tx*6 + 4];
            float bq[6] = {b01.x, b01.y, b23.x, b23.y, b45.x, b45.y};
            #pragma unroll
            for (int pp = 0; pp < 4; pp++)
                #pragma unroll
                for (int ii = 0; ii < 6; ii++)
                    sa[pp][ii] += a[pp] * bq[ii];
        }
        #pragma unroll
        for (int pp = 0; pp < 4; pp++) {
            int j = j0 + ty*4 + pp;
            #pragma unroll
            for (int ii = 0; ii < 6; ii++) {
                int i = tx*6 + ii;
                if (i < HWW && j < nvalid) S[j*85 + i] = sa[pp][ii] * INV_TEMP;
            }
        }
        __syncthreads();
    }

    // phase 2: softmax over j per query i
    {
        int i = tid >> 1, h = tid & 1;
        float mx = -1e30f, sum = 0.f;
        if (i < HWW) {
            for (int j = h; j < nvalid; j += 2) mx = fmaxf(mx, S[j*85 + i]);
        }
        mx = fmaxf(mx, __shfl_xor_sync(0xffffffffu, mx, 1));
        if (i < HWW) {
            for (int j = h; j < nvalid; j += 2) {
                float e = __expf(S[j*85 + i] - mx);
                S[j*85 + i] = e;
                sum += e;
            }
        }
        sum += __shfl_xor_sync(0xffffffffu, sum, 1);
        if (i < HWW && h == 0) invs[i] = 1.f / sum;
    }
    __syncthreads();

    // phase 3: PV
    int warp = tid >> 5, lane = tid & 31;
    int c0 = warp * 4;
    float acc[4][3] = {};
    for (int j = 0; j < nvalid; j += 4) {
        float4 v[4];
        #pragma unroll
        for (int cc = 0; cc < 4; cc++)
            v[cc] = *(const float4*)&Vs[(c0 + cc)*DM + j];
        #pragma unroll
        for (int q = 0; q < 4; q++) {
            const float* Sr = &S[(j + q)*85];
            float s0 = Sr[lane];
            float s1 = Sr[lane + 32];
            float s2 = (lane < HWW - 64) ? Sr[lane + 64] : 0.f;
            #pragma unroll
            for (int cc = 0; cc < 4; cc++) {
                float vq = (q == 0) ? v[cc].x : (q == 1) ? v[cc].y
                         : (q == 2) ? v[cc].z : v[cc].w;
                acc[cc][0] += vq * s0;
                acc[cc][1] += vq * s1;
                acc[cc][2] += vq * s2;
            }
        }
    }
    #pragma unroll
    for (int cc = 0; cc < 4; cc++) {
        long long o = base + (long long)(c0 + cc)*DM + ti*HWW;
        #pragma unroll
        for (int r = 0; r < 3; r++) {
            int i = lane + r*32;
            if (i < HWW) dvatt[o + i] = acc[cc][r] * invs[i];
        }
    }
}

// ---------------- fused obs attention per (b,t,n) ----------------
#define PCH 64
__global__ __launch_bounds__(256)
void obs_attn_kernel(const float* __restrict__ dk,
                     const float* __restrict__ dvatt,
                     const float* __restrict__ ok,
                     const float* __restrict__ ov,
                     const float* __restrict__ oq,
                     __nv_bfloat16* __restrict__ pvhi,
                     __nv_bfloat16* __restrict__ pvlo)
{
    int n = blockIdx.x, t = blockIdx.y, b = blockIdx.z;
    const long long obase = ((long long)b*FF + n*CH) * OM + (long long)t*HWW;
    const long long dbase = ((long long)b*FF + n*CH) * DM;

    __shared__ float qs[CH][HWW];     // rows 336B (8B-aligned at col*4 with col even)
    __shared__ float ks[CH][PCH];     // rows 256B (16B-aligned)
    __shared__ float vs[CH][PCH];
    __shared__ float S[PCH][HWW+1];

    int tid = threadIdx.x;
    int tx = tid % 16, ty = tid / 16;
    int warp = tid >> 5, lane = tid & 31;
    int c0 = warp * 4;

    for (int l = tid; l < CH*HWW; l += 256) {
        int c = l / HWW, j = l % HWW;
        qs[c][j] = oq[obase + (long long)c*OM + j];
    }

    float acc[4][3] = {};

    for (int p0 = 0; p0 < CATP; p0 += PCH) {
        for (int l = tid; l < CH*PCH; l += 256) {
            int c = l / PCH, pl = l % PCH;
            int p = p0 + pl;
            float kk = 0.f, vv = 0.f;
            if (p < DM) {
                kk = dk   [dbase + (long long)c*DM + p];
                vv = dvatt[dbase + (long long)c*DM + p];
            } else if (p < CATP) {
                kk = ok[obase + (long long)c*OM + (p - DM)];
                vv = ov[obase + (long long)c*OM + (p - DM)];
            }
            ks[c][pl] = kk; vs[c][pl] = vv;
        }
        __syncthreads();

        // logits: vectorized smem operand loads
        {
            float sa[4][6] = {};
            #pragma unroll
            for (int k = 0; k < CH; k++) {
                // ks row 16B-aligned at ty*4: one LDS.128
                float4 a4 = *(const float4*)&ks[k][ty*4];
                float a[4] = {a4.x, a4.y, a4.z, a4.w};
                // qs at tx*6: three LDS.64 (over-read past j=83 lands in ks —
                // in-bounds smem, discarded at store)
                float2 b01 = *(const float2*)&qs[k][tx*6];
                float2 b23 = *(const float2*)&qs[k][tx*6 + 2];
                float2 b45 = *(const float2*)&qs[k][tx*6 + 4];
                float bq[6] = {b01.x, b01.y, b23.x, b23.y, b45.x, b45.y};
                #pragma unroll
                for (int pp = 0; pp < 4; pp++)
                    #pragma unroll
                    for (int jj = 0; jj < 6; jj++)
                        sa[pp][jj] += a[pp] * bq[jj];
            }
            #pragma unroll
            for (int pp = 0; pp < 4; pp++)
                #pragma unroll
                for (int jj = 0; jj < 6; jj++) {
                    int j = tx*6 + jj;
                    if (j < HWW) S[ty*4 + pp][j] = sa[pp][jj] * INV_TEMP;
                }
        }
        __syncthreads();

        {
            int row = tid >> 2;
            int l4  = tid & 3;
            float mx = -1e30f;
            for (int j = l4; j < HWW; j += 4) mx = fmaxf(mx, S[row][j]);
            mx = fmaxf(mx, __shfl_xor_sync(0xffffffffu, mx, 1));
            mx = fmaxf(mx, __shfl_xor_sync(0xffffffffu, mx, 2));
            float sum = 0.f;
            for (int j = l4; j < HWW; j += 4) {
                float e = __expf(S[row][j] - mx);
                S[row][j] = e;
                sum += e;
            }
            sum += __shfl_xor_sync(0xffffffffu, sum, 1);
            sum += __shfl_xor_sync(0xffffffffu, sum, 2);
            float iv = 1.f / sum;
            bool valid = (p0 + row) < CATP;
            for (int j = l4; j < HWW; j += 4)
                S[row][j] = valid ? S[row][j] * iv : 0.f;
        }
        __syncthreads();

        #pragma unroll 2
        for (int pl = 0; pl < PCH; pl += 4) {
            float4 v[4];
            #pragma unroll
            for (int cc = 0; cc < 4; cc++)
                v[cc] = *(const float4*)&vs[c0 + cc][pl];
            #pragma unroll
            for (int q = 0; q < 4; q++) {
                float s0 = S[pl + q][lane];
                float s1 = S[pl + q][lane + 32];
                float s2 = (lane < HWW - 64) ? S[pl + q][lane + 64] : 0.f;
                #pragma unroll
                for (int cc = 0; cc < 4; cc++) {
                    float vq = (q == 0) ? v[cc].x : (q == 1) ? v[cc].y
                             : (q == 2) ? v[cc].z : v[cc].w;
                    acc[cc][0] += vq * s0;
                    acc[cc][1] += vq * s1;
                    acc[cc][2] += vq * s2;
                }
            }
        }
        __syncthreads();
    }

    #pragma unroll
    for (int cc = 0; cc < 4; cc++) {
        long long o = obase + (long long)(c0 + cc)*OM;
        #pragma unroll
        for (int r = 0; r < 3; r++) {
            int j = lane + r*32;
            if (j < HWW) {
                float vv = acc[cc][r];
                __nv_bfloat16 h = __float2bfloat16(vv);
                pvhi[o + j] = h;
                pvlo[o + j] = __float2bfloat16(vv - __bfloat162float(h));
            }
        }
    }
}

// ---------------- batchnorm + optional fused bf16 hi/lo split of the output ----------------
__global__ void bn_kernel(const float* __restrict__ x, float* __restrict__ out,
                          const float* __restrict__ gamma, const float* __restrict__ beta,
                          __nv_bfloat16* __restrict__ hi, __nv_bfloat16* __restrict__ lo)
{
    int ch = blockIdx.x;
    int tid = threadIdx.x;
    const long long chOff = (long long)ch * SPAT;

    double s = 0.0, s2 = 0.0;
    for (int b = 0; b < BB; b++) {
        const float* p = x + (long long)b*DD*SPAT + chOff;
        for (int idx = tid; idx < SPAT; idx += 256) {
            float v = p[idx];
            s  += v;
            s2 += (double)v * v;
        }
    }
    __shared__ double rs[256], rs2[256];
    rs[tid] = s; rs2[tid] = s2; __syncthreads();
    for (int o = 128; o > 0; o >>= 1) {
        if (tid < o) { rs[tid] += rs[tid+o]; rs2[tid] += rs2[tid+o]; }
        __syncthreads();
    }
    const double cnt = (double)BB * SPAT;
    double mean = rs[0] / cnt;
    double var  = rs2[0] / cnt - mean*mean;
    float scale = (float)((double)gamma[ch] * rsqrt(var + 1e-5));
    float mn = (float)mean;
    float bt = beta[ch];
    for (int b = 0; b < BB; b++) {
        const long long off = (long long)b*DD*SPAT + chOff;
        const float* p = x + off;
        float*       q = out + off;
        for (int idx = tid; idx < SPAT; idx += 256) {
            float y = scale * (p[idx] - mn) + bt;
            q[idx] = y;
            if (hi) {
                __nv_bfloat16 h = __float2bfloat16(y);
                hi[off + idx] = h;
                lo[off + idx] = __float2bfloat16(y - __bfloat162float(h));
            }
        }
    }
}

// ---------------- host driver ----------------
extern "C" void kernel_launch(void* const* d_in, const int* in_sizes, int n_in,
                              void* d_out, int out_size)
{
    const float* inputs  = (const float*)d_in[0];
    const float* demo_wq = (const float*)d_in[1];
    const float* demo_wk = (const float*)d_in[2];
    const float* demo_wv = (const float*)d_in[3];
    // demo_wo (d_in[4]) unused by the reference
    const float* obs_wq  = (const float*)d_in[5];
    const float* obs_wk  = (const float*)d_in[6];
    const float* obs_wv  = (const float*)d_in[7];
    const float* obs_wo  = (const float*)d_in[8];
    const float* bn_g    = (const float*)d_in[9];
    const float* bn_b    = (const float*)d_in[10];
    float* out = (float*)d_out;

    float *xp, *dqp, *dkp, *dvp, *dvattp, *oqp, *okp, *ovp;
    __nv_bfloat16 *xhip, *xlop, *pvhip, *pvlop, *wqhip, *wqlop, *wohip, *wolop;
    cudaGetSymbolAddress((void**)&xp,     g_x);
    cudaGetSymbolAddress((void**)&dqp,    g_dq);
    cudaGetSymbolAddress((void**)&dkp,    g_dk);
    cudaGetSymbolAddress((void**)&dvp,    g_dv);
    cudaGetSymbolAddress((void**)&dvattp, g_dvatt);
    cudaGetSymbolAddress((void**)&oqp,    g_oq);
    cudaGetSymbolAddress((void**)&okp,    g_ok);
    cudaGetSymbolAddress((void**)&ovp,    g_ov);
    cudaGetSymbolAddress((void**)&xhip,   g_xhi);
    cudaGetSymbolAddress((void**)&xlop,   g_xlo);
    cudaGetSymbolAddress((void**)&pvhip,  g_pvhi);
    cudaGetSymbolAddress((void**)&pvlop,  g_pvlo);
    cudaGetSymbolAddress((void**)&wqhip,  g_wqhi);
    cudaGetSymbolAddress((void**)&wqlop,  g_wqlo);
    cudaGetSymbolAddress((void**)&wohip,  g_wohi);
    cudaGetSymbolAddress((void**)&wolop,  g_wolo);

    // demo_attn needs ~177KB dynamic smem (config call, not an allocation)
    cudaFuncSetAttribute(demo_attn_kernel,
                         cudaFuncAttributeMaxDynamicSharedMemorySize, DSM_BYTES);

    cudaMemcpyAsync(xp, inputs, (size_t)BB*DD*SPAT*sizeof(float),
                    cudaMemcpyDeviceToDevice, 0);

    // convert all 7 weight tensors in one launch
    const int WT = 2*FF*DD;
    cvt_weights<<<dim3(WT/256, 7), 256>>>(demo_wq, demo_wk, demo_wv,
                                          obs_wq, obs_wk, obs_wv, obs_wo,
                                          wqhip, wqlop, wohip, wolop, WT);

    const long long XEL = (long long)BB*DD*SPAT;
    const long long XB  = (long long)DD*SPAT;
    const long long QD  = (long long)FF*DM;
    const long long QO  = (long long)FF*OM;

    // initial bf16 split of x (layer 1's split is fused into bn_kernel)
    cvt_pair<<<(unsigned)((XEL + 255)/256), 256>>>(xp, xhip, xlop, (int)XEL);

    for (int i = 0; i < 2; i++) {
        const long long lw = (long long)i*FF*DD;

        // demo QKV (tensor cores)
        wmma_qkv<<<dim3(3, (DM + 127)/128, BB), 256>>>(
            wqhip + lw, wqlop + lw, xhip, xlop,
            dqp, dkp, dvp, DM, SPAT, XB, QD);

        // blocked demo attention + dv_att
        demo_attn_kernel<<<dim3(DEMO_TT, NH, BB), 256, DSM_BYTES>>>(dkp, dqp, dvp, dvattp);

        // obs QKV
        wmma_qkv<<<dim3(3, OM/128, BB), 256>>>(
            wqhip + 3LL*WT + lw, wqlop + 3LL*WT + lw, xhip + DM, xlop + DM,
            oqp, okp, ovp, OM, SPAT, XB, QO);

        // obs attention -> pv bf16 hi/lo directly
        obs_attn_kernel<<<dim3(NH, OBS_TT, BB), 256>>>(dkp, dvattp, okp, ovp, oqp,
                                                       pvhip, pvlop);

        // output projection + residual + relu into x
        wmma_wo<<<dim3(DD/128, OM/128, BB), 256>>>(
            wohip + lw, wolop + lw, pvhip, pvlop, xp);

        // batchnorm; layer 0 also emits next layer's bf16 split
        bn_kernel<<<DD, 256>>>(xp, (i == 1) ? out : xp, bn_g + i*DD, bn_b + i*DD,
                               (i == 0) ? xhip : (__nv_bfloat16*)nullptr,
                               (i == 0) ? xlop : (__nv_bfloat16*)nullptr);
    }
}